// round 3
// baseline (speedup 1.0000x reference)
#include <cuda_runtime.h>
#include <cstdint>

// Problem constants: B=1024, T=512, I=256, H=256, 3H=768
#define Bsz  1024
#define Tsz  512
#define Isz  256
#define Hsz  256
#define Gsz  768
#define K2   512   // fused K = I + H
#define BM   8     // batch rows per CTA

// Fused weights, transposed for per-thread contiguous k-streaming:
// g_W2[g][k], g in [0,768): gate rows (r:0-255, z:256-511, n:512-767)
//            k in [0,512): 0-255 = input features (W_ih), 256-511 = hidden (W_hh)
__device__ float g_W2[Gsz * K2];
// g_bias: [0..255]=b_r (ih+hh), [256..511]=b_z (ih+hh), [512..767]=b_ih_n, [768..1023]=b_hh_n
__device__ float g_bias[4 * 256];

typedef unsigned long long ull;

__device__ __forceinline__ ull pack2(float x, float y) {
    ull r;
    asm("mov.b64 %0, {%1, %2};" : "=l"(r) : "f"(x), "f"(y));
    return r;
}
__device__ __forceinline__ void unpk2(ull v, float& x, float& y) {
    asm("mov.b64 {%0, %1}, %2;" : "=f"(x), "=f"(y) : "l"(v));
}
// Packed 2xFP32 FMA (PTX-only on sm_10x; ptxas never auto-fuses).
__device__ __forceinline__ void fma2(ull& d, ull a, ull b) {
    asm("fma.rn.f32x2 %0, %1, %2, %3;" : "=l"(d) : "l"(a), "l"(b), "l"(d));
}

__global__ void prep_kernel(const float* __restrict__ W_ih, const float* __restrict__ W_hh,
                            const float* __restrict__ b_ih, const float* __restrict__ b_hh) {
    int idx = blockIdx.x * blockDim.x + threadIdx.x;
    if (idx < Gsz * K2) {
        int g = idx / K2;
        int k = idx - g * K2;
        g_W2[idx] = (k < Isz) ? W_ih[g * Isz + k] : W_hh[g * Hsz + (k - Isz)];
    }
    if (idx < 256) {
        g_bias[idx]       = b_ih[idx]       + b_hh[idx];        // r
        g_bias[256 + idx] = b_ih[256 + idx] + b_hh[256 + idx];  // z
        g_bias[512 + idx] = b_ih[512 + idx];                    // xn (x-part of n)
        g_bias[768 + idx] = b_hh[512 + idx];                    // hg (h-part of n)
    }
}

// Accumulate 256 k-steps of one half (x-part or h-part) of the fused GEMM.
// Weights stream as float4 with a 2-deep prefetch pipeline; xh rows broadcast via LDS.128.
__device__ __forceinline__ void half_gemm(
    const float4* __restrict__ Wr4, const float4* __restrict__ Wz4,
    const float4* __restrict__ Wn4, const float (*xh)[BM], int kbase,
    ull* aR, ull* aZ, ull* aN)
{
    float4 r0 = Wr4[0], z0 = Wz4[0], n0 = Wn4[0];
    float4 r1 = Wr4[1], z1 = Wz4[1], n1 = Wn4[1];
#pragma unroll 2
    for (int kk = 0; kk < 64; kk++) {
        float4 rc = r0, zc = z0, nc = n0;
        r0 = r1; z0 = z1; n0 = n1;
        int nx = kk + 2;
        if (nx < 64) { r1 = Wr4[nx]; z1 = Wz4[nx]; n1 = Wn4[nx]; }
        float wrs[4] = {rc.x, rc.y, rc.z, rc.w};
        float wzs[4] = {zc.x, zc.y, zc.z, zc.w};
        float wns[4] = {nc.x, nc.y, nc.z, nc.w};
#pragma unroll
        for (int j = 0; j < 4; j++) {
            ull wr2 = pack2(wrs[j], wrs[j]);
            ull wz2 = pack2(wzs[j], wzs[j]);
            ull wn2 = pack2(wns[j], wns[j]);
            const ulonglong2* xp =
                reinterpret_cast<const ulonglong2*>(&xh[kbase + kk * 4 + j][0]);
            ulonglong2 v0 = xp[0], v1 = xp[1];
            fma2(aR[0], v0.x, wr2); fma2(aZ[0], v0.x, wz2); fma2(aN[0], v0.x, wn2);
            fma2(aR[1], v0.y, wr2); fma2(aZ[1], v0.y, wz2); fma2(aN[1], v0.y, wn2);
            fma2(aR[2], v1.x, wr2); fma2(aZ[2], v1.x, wz2); fma2(aN[2], v1.x, wn2);
            fma2(aR[3], v1.y, wr2); fma2(aZ[3], v1.y, wz2); fma2(aN[3], v1.y, wn2);
        }
    }
}

// One CTA per 8 batch rows; h lives in SMEM rows [256..511] of xh for all 512 steps.
// Thread c owns output column c. Per step: 6144 FFMA2, 384 LDG.128, 1024 LDS.128 per thread.
__global__ void __launch_bounds__(256, 1) gru_kernel(const float* __restrict__ x,
                                                     const int* __restrict__ seqlen,
                                                     float* __restrict__ out) {
    __shared__ __align__(16) float xh[K2][BM];  // [0..255]=x_t, [256..511]=h; layout [k][b]

    const int c  = threadIdx.x;
    const int b0 = blockIdx.x * BM;

    int   L[BM];
    float hn[BM], xv[BM], xvn[BM];
    const float* xp[BM];
#pragma unroll
    for (int b = 0; b < BM; b++) {
        L[b]  = seqlen[b0 + b];
        hn[b] = 0.0f;
        xh[Isz + c][b] = 0.0f;                              // h = 0
        xp[b] = x + ((size_t)(b0 + b) * Tsz) * Isz + c;     // x[b][t=0][c]
        xv[b] = xp[b][0];                                   // preload t=0
    }
    const float br  = g_bias[c];
    const float bz  = g_bias[256 + c];
    const float bxn = g_bias[512 + c];
    const float bhg = g_bias[768 + c];

    const float4* Wr4 = reinterpret_cast<const float4*>(g_W2 + (size_t)c * K2);
    const float4* Wz4 = reinterpret_cast<const float4*>(g_W2 + (size_t)(256 + c) * K2);
    const float4* Wn4 = reinterpret_cast<const float4*>(g_W2 + (size_t)(512 + c) * K2);

#pragma unroll 1
    for (int t = 0; t < Tsz; t++) {
        // publish x_t (column c for all 8 rows)
#pragma unroll
        for (int b = 0; b < BM; b++) xh[c][b] = xv[b];
        __syncthreads();  // x writes + previous step's h writes visible

        // prefetch next step's x (DRAM latency hides behind the k-loops)
        if (t + 1 < Tsz) {
#pragma unroll
            for (int b = 0; b < BM; b++) xvn[b] = xp[b][(t + 1) * Isz];
        }

        ull aR[4], aZ[4], aXN[4], aHG[4];
#pragma unroll
        for (int p = 0; p < 4; p++) {
            aR[p]  = pack2(br, br);
            aZ[p]  = pack2(bz, bz);
            aXN[p] = pack2(bxn, bxn);
            aHG[p] = pack2(bhg, bhg);
        }

        half_gemm(Wr4,      Wz4,      Wn4,      xh, 0,   aR, aZ, aXN);  // k 0..255   (x part)
        half_gemm(Wr4 + 64, Wz4 + 64, Wn4 + 64, xh, Isz, aR, aZ, aHG);  // k 256..511 (h part)

        __syncthreads();  // all reads of h rows done before overwrite

#pragma unroll
        for (int p = 0; p < 4; p++) {
            float rv[2], zv[2], xn[2], hg[2];
            unpk2(aR[p],  rv[0], rv[1]);
            unpk2(aZ[p],  zv[0], zv[1]);
            unpk2(aXN[p], xn[0], xn[1]);
            unpk2(aHG[p], hg[0], hg[1]);
#pragma unroll
            for (int e = 0; e < 2; e++) {
                int b = 2 * p + e;
                float r = 1.0f / (1.0f + expf(-rv[e]));
                float z = 1.0f / (1.0f + expf(-zv[e]));
                float n = tanhf(xn[e] + r * hg[e]);
                float hold = xh[Isz + c][b];
                float hnew = (1.0f - z) * n + z * hold;
                xh[Isz + c][b] = hnew;
                if (t + 1 == L[b]) hn[b] = hnew;
            }
        }
#pragma unroll
        for (int b = 0; b < BM; b++) xv[b] = xvn[b];
        // next iteration's first __syncthreads orders the h writes
    }

#pragma unroll
    for (int b = 0; b < BM; b++)
        out[(b0 + b) * Hsz + c] = hn[b];  // L==0 rows output 0
}

extern "C" void kernel_launch(void* const* d_in, const int* in_sizes, int n_in,
                              void* d_out, int out_size) {
    const float* x      = (const float*)d_in[0];  // [B,T,I]
    const int*   seqlen = (const int*)d_in[1];    // [B]
    const float* W_ih   = (const float*)d_in[2];  // [3H,I]
    const float* W_hh   = (const float*)d_in[3];  // [3H,H]
    const float* b_ih   = (const float*)d_in[4];  // [3H]
    const float* b_hh   = (const float*)d_in[5];  // [3H]
    float*       out    = (float*)d_out;          // [B,H]

    prep_kernel<<<(Gsz * K2 + 255) / 256, 256>>>(W_ih, W_hh, b_ih, b_hh);
    gru_kernel<<<Bsz / BM, 256>>>(x, seqlen, out);
}

// round 4
// speedup vs baseline: 2.0327x; 2.0327x over previous
#include <cuda_runtime.h>
#include <cstdint>

// Problem constants: B=1024, T=512, I=256, H=256, 3H=768
#define Bsz  1024
#define Tsz  512
#define Isz  256
#define Hsz  256
#define Gsz  768
#define K2   512   // fused K = I + H
#define BM   8     // batch rows per CTA
#define NQ   128   // k-quads total (K2/4)

typedef unsigned long long ull;

// Weights interleaved over k-quads, gate-column-major:
// g_W4[q*Gsz + g] = {W[4q][g], W[4q+1][g], W[4q+2][g], W[4q+3][g]}
// where fused k: k<256 -> W_ih[g][k], k>=256 -> W_hh[g][k-256].
// Stored as ulonglong2 so LDG.128 lands directly in packed-f32x2 form.
__device__ ulonglong2 g_W4[NQ * Gsz];
// g_bias: [0..255]=b_r(ih+hh), [256..511]=b_z(ih+hh), [512..767]=b_ih_n, [768..1023]=b_hh_n
__device__ float g_bias[4 * 256];

__device__ __forceinline__ void fma2(ull& d, ull a, ull b) {
    asm("fma.rn.f32x2 %0, %1, %2, %3;" : "=l"(d) : "l"(a), "l"(b), "l"(d));
}
__device__ __forceinline__ ull add2(ull a, ull b) {
    ull d;
    asm("add.rn.f32x2 %0, %1, %2;" : "=l"(d) : "l"(a), "l"(b));
    return d;
}
__device__ __forceinline__ float hsum2(ull v) {
    float x, y;
    asm("mov.b64 {%0, %1}, %2;" : "=f"(x), "=f"(y) : "l"(v));
    return x + y;
}
__device__ __forceinline__ float sigm(float a) {
    return __fdividef(1.0f, 1.0f + __expf(-a));
}
__device__ __forceinline__ float tanh_(float u) {
    return 1.0f - __fdividef(2.0f, 1.0f + __expf(2.0f * u));
}

__global__ void prep_kernel(const float* __restrict__ W_ih, const float* __restrict__ W_hh,
                            const float* __restrict__ b_ih, const float* __restrict__ b_hh) {
    int idx = blockIdx.x * blockDim.x + threadIdx.x;  // over NQ*Gsz*4 floats
    if (idx < NQ * Gsz * 4) {
        int e  = idx & 3;
        int gq = idx >> 2;
        int g  = gq % Gsz;
        int q  = gq / Gsz;
        int k  = q * 4 + e;
        float v = (k < Isz) ? W_ih[g * Isz + k] : W_hh[g * Hsz + (k - Isz)];
        reinterpret_cast<float*>(g_W4)[idx] = v;
    }
    if (idx < 256) {
        g_bias[idx]       = b_ih[idx]       + b_hh[idx];        // r
        g_bias[256 + idx] = b_ih[256 + idx] + b_hh[256 + idx];  // z
        g_bias[512 + idx] = b_ih[512 + idx];                    // xn
        g_bias[768 + idx] = b_hh[512 + idx];                    // hg
    }
}

// Dynamic SMEM layout:
//   float xh[BM][K2]          (16 KB)  [b][k]: k 0..255 = x_t, 256..511 = h
//   ull   red[24][256]        (48 KB)  kh=1 partials, j = gate*8 + b
#define SMEM_BYTES (BM * K2 * 4 + 24 * 256 * 8)

// 512 threads: c = tid&255 (output column), kh = tid>>8 (k-half).
// kh=0 accumulates x-part (k 0..255), kh=1 accumulates h-part (k 256..511).
// kh=0 finishes gates + h update; kh=1 stages next x.
__global__ void __launch_bounds__(512, 1) gru_kernel(const float* __restrict__ x,
                                                     const int* __restrict__ seqlen,
                                                     float* __restrict__ out) {
    extern __shared__ __align__(16) char smem_raw[];
    float* xh  = reinterpret_cast<float*>(smem_raw);                 // [BM][K2]
    ull*   red = reinterpret_cast<ull*>(smem_raw + BM * K2 * 4);     // [24][256]

    const int c  = threadIdx.x & 255;
    const int kh = threadIdx.x >> 8;
    const int b0 = blockIdx.x * BM;

    // Weight streams for this thread: 64 quads, stride Gsz per quad.
    const ulonglong2* __restrict__ Wr = g_W4 + (size_t)(kh * 64) * Gsz + c;
    const ulonglong2* __restrict__ Wz = Wr + 256;
    const ulonglong2* __restrict__ Wn = Wr + 512;

    int   L[BM];
    float hn[BM], hreg[BM], xvn[BM];
    const float* xc = x + (size_t)b0 * Tsz * Isz + c;

    if (kh == 0) {
#pragma unroll
        for (int b = 0; b < BM; b++) {
            L[b] = seqlen[b0 + b];
            hn[b] = 0.0f;
            hreg[b] = 0.0f;
            xh[b * K2 + Isz + c] = 0.0f;   // h = 0
        }
    } else {
#pragma unroll
        for (int b = 0; b < BM; b++)
            xh[b * K2 + c] = xc[(size_t)b * Tsz * Isz];  // x_0
    }
    const float br  = g_bias[c];
    const float bz  = g_bias[256 + c];
    const float bxn = g_bias[512 + c];
    const float bhg = g_bias[768 + c];
    const int kbase = kh * Isz;
    __syncthreads();

#pragma unroll 1
    for (int t = 0; t < Tsz; t++) {
        // prefetch next x (kh=1 only; DRAM latency hides behind the GEMM)
        if (kh == 1 && t + 1 < Tsz) {
#pragma unroll
            for (int b = 0; b < BM; b++)
                xvn[b] = xc[((size_t)b * Tsz + (t + 1)) * Isz];
        }

        // accumulators: lanes = (even-k, odd-k) partial sums; acc[gate][b]
        ull acc[3][BM];
#pragma unroll
        for (int g = 0; g < 3; g++)
#pragma unroll
            for (int b = 0; b < BM; b++) acc[g][b] = 0ULL;

        // 4-deep weight prefetch pipeline over 64 quads
        ulonglong2 wr[4], wz[4], wn[4];
#pragma unroll
        for (int p = 0; p < 4; p++) {
            wr[p] = Wr[p * Gsz];
            wz[p] = Wz[p * Gsz];
            wn[p] = Wn[p * Gsz];
        }
#pragma unroll 4
        for (int q = 0; q < 64; q++) {
            const int s = q & 3;
            ulonglong2 cwr = wr[s], cwz = wz[s], cwn = wn[s];
            if (q + 4 < 64) {
                wr[s] = Wr[(q + 4) * Gsz];
                wz[s] = Wz[(q + 4) * Gsz];
                wn[s] = Wn[(q + 4) * Gsz];
            }
#pragma unroll
            for (int b = 0; b < BM; b++) {
                // broadcast LDS.128: 4 consecutive k of row b
                ulonglong2 v = *reinterpret_cast<const ulonglong2*>(
                    &xh[b * K2 + kbase + q * 4]);
                fma2(acc[0][b], v.x, cwr.x);
                fma2(acc[1][b], v.x, cwz.x);
                fma2(acc[2][b], v.x, cwn.x);
                fma2(acc[0][b], v.y, cwr.y);
                fma2(acc[1][b], v.y, cwz.y);
                fma2(acc[2][b], v.y, cwn.y);
            }
        }

        // publish h-part partials
        if (kh == 1) {
#pragma unroll
            for (int g = 0; g < 3; g++)
#pragma unroll
                for (int b = 0; b < BM; b++)
                    red[(g * BM + b) * 256 + c] = acc[g][b];
        }
        __syncthreads();

        if (kh == 0) {
            // combine halves, gates, h update
#pragma unroll
            for (int b = 0; b < BM; b++) {
                ull pr = red[(0 * BM + b) * 256 + c];
                ull pz = red[(1 * BM + b) * 256 + c];
                ull pg = red[(2 * BM + b) * 256 + c];
                float r  = sigm(hsum2(add2(acc[0][b], pr)) + br);
                float z  = sigm(hsum2(add2(acc[1][b], pz)) + bz);
                float xn = hsum2(acc[2][b]) + bxn;
                float hg = hsum2(pg) + bhg;
                float n  = tanh_(xn + r * hg);
                float hnew = z * (hreg[b] - n) + n;   // (1-z)n + z h
                hreg[b] = hnew;
                xh[b * K2 + Isz + c] = hnew;
                if (t + 1 == L[b]) hn[b] = hnew;
            }
        } else {
            // stage x_{t+1}
            if (t + 1 < Tsz) {
#pragma unroll
                for (int b = 0; b < BM; b++)
                    xh[b * K2 + c] = xvn[b];
            }
        }
        __syncthreads();
    }

    if (kh == 0) {
#pragma unroll
        for (int b = 0; b < BM; b++)
            out[(size_t)(b0 + b) * Hsz + c] = hn[b];  // L==0 rows stay 0
    }
}

extern "C" void kernel_launch(void* const* d_in, const int* in_sizes, int n_in,
                              void* d_out, int out_size) {
    const float* x      = (const float*)d_in[0];  // [B,T,I]
    const int*   seqlen = (const int*)d_in[1];    // [B]
    const float* W_ih   = (const float*)d_in[2];  // [3H,I]
    const float* W_hh   = (const float*)d_in[3];  // [3H,H]
    const float* b_ih   = (const float*)d_in[4];  // [3H]
    const float* b_hh   = (const float*)d_in[5];  // [3H]
    float*       out    = (float*)d_out;          // [B,H]

    static bool attr_set = false;
    if (!attr_set) {
        cudaFuncSetAttribute(gru_kernel, cudaFuncAttributeMaxDynamicSharedMemorySize,
                             SMEM_BYTES);
        attr_set = true;
    }
    prep_kernel<<<(NQ * Gsz * 4 + 255) / 256, 256>>>(W_ih, W_hh, b_ih, b_hh);
    gru_kernel<<<Bsz / BM, 512, SMEM_BYTES>>>(x, seqlen, out);
}

// round 5
// speedup vs baseline: 2.0353x; 1.0012x over previous
#include <cuda_runtime.h>
#include <cstdint>

// Problem constants: B=1024, T=512, I=256, H=256, 3H=768
#define Bsz  1024
#define Tsz  512
#define Isz  256
#define Hsz  256
#define Gsz  768
#define K2   512   // fused K = I + H
#define BM   8     // batch rows per CTA
#define NQ   128   // k-quads total (K2/4)

typedef unsigned long long ull;

// Weights interleaved over k-quads, gate-column-major:
// g_W4[q*Gsz + g] = {W[4q][g], W[4q+1][g], W[4q+2][g], W[4q+3][g]}
// where fused k: k<256 -> W_ih[g][k], k>=256 -> W_hh[g][k-256].
// Stored as ulonglong2 so LDG.128 lands directly in packed-f32x2 form.
__device__ ulonglong2 g_W4[NQ * Gsz];
// g_bias: [0..255]=b_r(ih+hh), [256..511]=b_z(ih+hh), [512..767]=b_ih_n, [768..1023]=b_hh_n
__device__ float g_bias[4 * 256];

__device__ __forceinline__ void fma2(ull& d, ull a, ull b) {
    asm("fma.rn.f32x2 %0, %1, %2, %3;" : "=l"(d) : "l"(a), "l"(b), "l"(d));
}
__device__ __forceinline__ ull add2(ull a, ull b) {
    ull d;
    asm("add.rn.f32x2 %0, %1, %2;" : "=l"(d) : "l"(a), "l"(b));
    return d;
}
__device__ __forceinline__ float hsum2(ull v) {
    float x, y;
    asm("mov.b64 {%0, %1}, %2;" : "=f"(x), "=f"(y) : "l"(v));
    return x + y;
}
__device__ __forceinline__ float sigm(float a) {
    return __fdividef(1.0f, 1.0f + __expf(-a));
}
__device__ __forceinline__ float tanh_(float u) {
    return 1.0f - __fdividef(2.0f, 1.0f + __expf(2.0f * u));
}

__global__ void prep_kernel(const float* __restrict__ W_ih, const float* __restrict__ W_hh,
                            const float* __restrict__ b_ih, const float* __restrict__ b_hh) {
    int idx = blockIdx.x * blockDim.x + threadIdx.x;  // over NQ*Gsz*4 floats
    if (idx < NQ * Gsz * 4) {
        int e  = idx & 3;
        int gq = idx >> 2;
        int g  = gq % Gsz;
        int q  = gq / Gsz;
        int k  = q * 4 + e;
        float v = (k < Isz) ? W_ih[g * Isz + k] : W_hh[g * Hsz + (k - Isz)];
        reinterpret_cast<float*>(g_W4)[idx] = v;
    }
    if (idx < 256) {
        g_bias[idx]       = b_ih[idx]       + b_hh[idx];        // r
        g_bias[256 + idx] = b_ih[256 + idx] + b_hh[256 + idx];  // z
        g_bias[512 + idx] = b_ih[512 + idx];                    // xn
        g_bias[768 + idx] = b_hh[512 + idx];                    // hg
    }
}

// Dynamic SMEM layout:
//   float xh[BM][K2]          (16 KB)  [b][k]: k 0..255 = x_t, 256..511 = h
//   ull   red[24][256]        (48 KB)  kh=1 partials, j = gate*8 + b
#define SMEM_BYTES (BM * K2 * 4 + 24 * 256 * 8)

// 512 threads: c = tid&255 (output column), kh = tid>>8 (k-half).
// kh=0 accumulates x-part (k 0..255), kh=1 accumulates h-part (k 256..511).
// kh=0 finishes gates + h update; kh=1 stages next x.
__global__ void __launch_bounds__(512, 1) gru_kernel(const float* __restrict__ x,
                                                     const int* __restrict__ seqlen,
                                                     float* __restrict__ out) {
    extern __shared__ __align__(16) char smem_raw[];
    float* xh  = reinterpret_cast<float*>(smem_raw);                 // [BM][K2]
    ull*   red = reinterpret_cast<ull*>(smem_raw + BM * K2 * 4);     // [24][256]

    const int c  = threadIdx.x & 255;
    const int kh = threadIdx.x >> 8;
    const int b0 = blockIdx.x * BM;

    // Weight streams for this thread: 64 quads, stride Gsz per quad.
    const ulonglong2* __restrict__ Wr = g_W4 + (size_t)(kh * 64) * Gsz + c;
    const ulonglong2* __restrict__ Wz = Wr + 256;
    const ulonglong2* __restrict__ Wn = Wr + 512;

    int   L[BM];
    float hn[BM], hreg[BM], xvn[BM];
    const float* xc = x + (size_t)b0 * Tsz * Isz + c;

    if (kh == 0) {
#pragma unroll
        for (int b = 0; b < BM; b++) {
            L[b] = seqlen[b0 + b];
            hn[b] = 0.0f;
            hreg[b] = 0.0f;
            xh[b * K2 + Isz + c] = 0.0f;   // h = 0
        }
    } else {
#pragma unroll
        for (int b = 0; b < BM; b++)
            xh[b * K2 + c] = xc[(size_t)b * Tsz * Isz];  // x_0
    }
    const float br  = g_bias[c];
    const float bz  = g_bias[256 + c];
    const float bxn = g_bias[512 + c];
    const float bhg = g_bias[768 + c];
    const int kbase = kh * Isz;
    __syncthreads();

#pragma unroll 1
    for (int t = 0; t < Tsz; t++) {
        // prefetch next x (kh=1 only; DRAM latency hides behind the GEMM)
        if (kh == 1 && t + 1 < Tsz) {
#pragma unroll
            for (int b = 0; b < BM; b++)
                xvn[b] = xc[((size_t)b * Tsz + (t + 1)) * Isz];
        }

        // accumulators: lanes = (even-k, odd-k) partial sums; acc[gate][b]
        ull acc[3][BM];
#pragma unroll
        for (int g = 0; g < 3; g++)
#pragma unroll
            for (int b = 0; b < BM; b++) acc[g][b] = 0ULL;

        // 4-deep weight prefetch pipeline over 64 quads
        ulonglong2 wr[4], wz[4], wn[4];
#pragma unroll
        for (int p = 0; p < 4; p++) {
            wr[p] = Wr[p * Gsz];
            wz[p] = Wz[p * Gsz];
            wn[p] = Wn[p * Gsz];
        }
#pragma unroll 4
        for (int q = 0; q < 64; q++) {
            const int s = q & 3;
            ulonglong2 cwr = wr[s], cwz = wz[s], cwn = wn[s];
            if (q + 4 < 64) {
                wr[s] = Wr[(q + 4) * Gsz];
                wz[s] = Wz[(q + 4) * Gsz];
                wn[s] = Wn[(q + 4) * Gsz];
            }
#pragma unroll
            for (int b = 0; b < BM; b++) {
                // broadcast LDS.128: 4 consecutive k of row b
                ulonglong2 v = *reinterpret_cast<const ulonglong2*>(
                    &xh[b * K2 + kbase + q * 4]);
                fma2(acc[0][b], v.x, cwr.x);
                fma2(acc[1][b], v.x, cwz.x);
                fma2(acc[2][b], v.x, cwn.x);
                fma2(acc[0][b], v.y, cwr.y);
                fma2(acc[1][b], v.y, cwz.y);
                fma2(acc[2][b], v.y, cwn.y);
            }
        }

        // publish h-part partials
        if (kh == 1) {
#pragma unroll
            for (int g = 0; g < 3; g++)
#pragma unroll
                for (int b = 0; b < BM; b++)
                    red[(g * BM + b) * 256 + c] = acc[g][b];
        }
        __syncthreads();

        if (kh == 0) {
            // combine halves, gates, h update
#pragma unroll
            for (int b = 0; b < BM; b++) {
                ull pr = red[(0 * BM + b) * 256 + c];
                ull pz = red[(1 * BM + b) * 256 + c];
                ull pg = red[(2 * BM + b) * 256 + c];
                float r  = sigm(hsum2(add2(acc[0][b], pr)) + br);
                float z  = sigm(hsum2(add2(acc[1][b], pz)) + bz);
                float xn = hsum2(acc[2][b]) + bxn;
                float hg = hsum2(pg) + bhg;
                float n  = tanh_(xn + r * hg);
                float hnew = z * (hreg[b] - n) + n;   // (1-z)n + z h
                hreg[b] = hnew;
                xh[b * K2 + Isz + c] = hnew;
                if (t + 1 == L[b]) hn[b] = hnew;
            }
        } else {
            // stage x_{t+1}
            if (t + 1 < Tsz) {
#pragma unroll
                for (int b = 0; b < BM; b++)
                    xh[b * K2 + c] = xvn[b];
            }
        }
        __syncthreads();
    }

    if (kh == 0) {
#pragma unroll
        for (int b = 0; b < BM; b++)
            out[(size_t)(b0 + b) * Hsz + c] = hn[b];  // L==0 rows stay 0
    }
}

extern "C" void kernel_launch(void* const* d_in, const int* in_sizes, int n_in,
                              void* d_out, int out_size) {
    const float* x      = (const float*)d_in[0];  // [B,T,I]
    const int*   seqlen = (const int*)d_in[1];    // [B]
    const float* W_ih   = (const float*)d_in[2];  // [3H,I]
    const float* W_hh   = (const float*)d_in[3];  // [3H,H]
    const float* b_ih   = (const float*)d_in[4];  // [3H]
    const float* b_hh   = (const float*)d_in[5];  // [3H]
    float*       out    = (float*)d_out;          // [B,H]

    static bool attr_set = false;
    if (!attr_set) {
        cudaFuncSetAttribute(gru_kernel, cudaFuncAttributeMaxDynamicSharedMemorySize,
                             SMEM_BYTES);
        attr_set = true;
    }
    prep_kernel<<<(NQ * Gsz * 4 + 255) / 256, 256>>>(W_ih, W_hh, b_ih, b_hh);
    gru_kernel<<<Bsz / BM, 512, SMEM_BYTES>>>(x, seqlen, out);
}

// round 6
// speedup vs baseline: 2.0405x; 1.0026x over previous
#include <cuda_runtime.h>
#include <cstdint>

// Problem constants: B=1024, T=512, I=256, H=256, 3H=768
#define Bsz  1024
#define Tsz  512
#define Isz  256
#define Hsz  256
#define Gsz  768
#define K2   512   // fused K = I + H
#define BM   8     // batch rows per CTA
#define NQ   128   // k-quads total (K2/4)

typedef unsigned long long ull;

// Weights interleaved over k-quads, gate-column-major:
// g_W4[q*Gsz + g] = {W[4q][g], W[4q+1][g], W[4q+2][g], W[4q+3][g]}
// where fused k: k<256 -> W_ih[g][k], k>=256 -> W_hh[g][k-256].
// Stored as ulonglong2 so LDG.128 lands directly in packed-f32x2 form.
__device__ ulonglong2 g_W4[NQ * Gsz];
// g_bias: [0..255]=b_r(ih+hh), [256..511]=b_z(ih+hh), [512..767]=b_ih_n, [768..1023]=b_hh_n
__device__ float g_bias[4 * 256];

__device__ __forceinline__ void fma2(ull& d, ull a, ull b) {
    asm("fma.rn.f32x2 %0, %1, %2, %3;" : "=l"(d) : "l"(a), "l"(b), "l"(d));
}
__device__ __forceinline__ ull add2(ull a, ull b) {
    ull d;
    asm("add.rn.f32x2 %0, %1, %2;" : "=l"(d) : "l"(a), "l"(b));
    return d;
}
__device__ __forceinline__ float hsum2(ull v) {
    float x, y;
    asm("mov.b64 {%0, %1}, %2;" : "=f"(x), "=f"(y) : "l"(v));
    return x + y;
}
__device__ __forceinline__ float sigm(float a) {
    return __fdividef(1.0f, 1.0f + __expf(-a));
}
__device__ __forceinline__ float tanh_(float u) {
    return 1.0f - __fdividef(2.0f, 1.0f + __expf(2.0f * u));
}

__global__ void prep_kernel(const float* __restrict__ W_ih, const float* __restrict__ W_hh,
                            const float* __restrict__ b_ih, const float* __restrict__ b_hh) {
    int idx = blockIdx.x * blockDim.x + threadIdx.x;  // over NQ*Gsz*4 floats
    if (idx < NQ * Gsz * 4) {
        int e  = idx & 3;
        int gq = idx >> 2;
        int g  = gq % Gsz;
        int q  = gq / Gsz;
        int k  = q * 4 + e;
        float v = (k < Isz) ? W_ih[g * Isz + k] : W_hh[g * Hsz + (k - Isz)];
        reinterpret_cast<float*>(g_W4)[idx] = v;
    }
    if (idx < 256) {
        g_bias[idx]       = b_ih[idx]       + b_hh[idx];        // r
        g_bias[256 + idx] = b_ih[256 + idx] + b_hh[256 + idx];  // z
        g_bias[512 + idx] = b_ih[512 + idx];                    // xn
        g_bias[768 + idx] = b_hh[512 + idx];                    // hg
    }
}

// Dynamic SMEM layout:
//   float xh[BM][K2]          (16 KB)  [b][k]: k 0..255 = x_t, 256..511 = h
//   ull   red[24][256]        (48 KB)  kh=1 partials, j = gate*8 + b
#define SMEM_BYTES (BM * K2 * 4 + 24 * 256 * 8)

// 512 threads: c = tid&255 (output column), kh = tid>>8 (k-half).
// kh=0 accumulates x-part (k 0..255), kh=1 accumulates h-part (k 256..511).
// kh=0 finishes gates + h update; kh=1 stages next x.
__global__ void __launch_bounds__(512, 1) gru_kernel(const float* __restrict__ x,
                                                     const int* __restrict__ seqlen,
                                                     float* __restrict__ out) {
    extern __shared__ __align__(16) char smem_raw[];
    float* xh  = reinterpret_cast<float*>(smem_raw);                 // [BM][K2]
    ull*   red = reinterpret_cast<ull*>(smem_raw + BM * K2 * 4);     // [24][256]

    const int c  = threadIdx.x & 255;
    const int kh = threadIdx.x >> 8;
    const int b0 = blockIdx.x * BM;

    // Weight streams for this thread: 64 quads, stride Gsz per quad.
    const ulonglong2* __restrict__ Wr = g_W4 + (size_t)(kh * 64) * Gsz + c;
    const ulonglong2* __restrict__ Wz = Wr + 256;
    const ulonglong2* __restrict__ Wn = Wr + 512;

    int   L[BM];
    float hn[BM], hreg[BM], xvn[BM];
    const float* xc = x + (size_t)b0 * Tsz * Isz + c;

    if (kh == 0) {
#pragma unroll
        for (int b = 0; b < BM; b++) {
            L[b] = seqlen[b0 + b];
            hn[b] = 0.0f;
            hreg[b] = 0.0f;
            xh[b * K2 + Isz + c] = 0.0f;   // h = 0
        }
    } else {
#pragma unroll
        for (int b = 0; b < BM; b++)
            xh[b * K2 + c] = xc[(size_t)b * Tsz * Isz];  // x_0
    }
    const float br  = g_bias[c];
    const float bz  = g_bias[256 + c];
    const float bxn = g_bias[512 + c];
    const float bhg = g_bias[768 + c];
    const int kbase = kh * Isz;
    __syncthreads();

#pragma unroll 1
    for (int t = 0; t < Tsz; t++) {
        // prefetch next x (kh=1 only; DRAM latency hides behind the GEMM)
        if (kh == 1 && t + 1 < Tsz) {
#pragma unroll
            for (int b = 0; b < BM; b++)
                xvn[b] = xc[((size_t)b * Tsz + (t + 1)) * Isz];
        }

        // accumulators: lanes = (even-k, odd-k) partial sums; acc[gate][b]
        ull acc[3][BM];
#pragma unroll
        for (int g = 0; g < 3; g++)
#pragma unroll
            for (int b = 0; b < BM; b++) acc[g][b] = 0ULL;

        // 4-deep weight prefetch pipeline over 64 quads
        ulonglong2 wr[4], wz[4], wn[4];
#pragma unroll
        for (int p = 0; p < 4; p++) {
            wr[p] = Wr[p * Gsz];
            wz[p] = Wz[p * Gsz];
            wn[p] = Wn[p * Gsz];
        }
#pragma unroll 4
        for (int q = 0; q < 64; q++) {
            const int s = q & 3;
            ulonglong2 cwr = wr[s], cwz = wz[s], cwn = wn[s];
            if (q + 4 < 64) {
                wr[s] = Wr[(q + 4) * Gsz];
                wz[s] = Wz[(q + 4) * Gsz];
                wn[s] = Wn[(q + 4) * Gsz];
            }
#pragma unroll
            for (int b = 0; b < BM; b++) {
                // broadcast LDS.128: 4 consecutive k of row b
                ulonglong2 v = *reinterpret_cast<const ulonglong2*>(
                    &xh[b * K2 + kbase + q * 4]);
                fma2(acc[0][b], v.x, cwr.x);
                fma2(acc[1][b], v.x, cwz.x);
                fma2(acc[2][b], v.x, cwn.x);
                fma2(acc[0][b], v.y, cwr.y);
                fma2(acc[1][b], v.y, cwz.y);
                fma2(acc[2][b], v.y, cwn.y);
            }
        }

        // publish h-part partials
        if (kh == 1) {
#pragma unroll
            for (int g = 0; g < 3; g++)
#pragma unroll
                for (int b = 0; b < BM; b++)
                    red[(g * BM + b) * 256 + c] = acc[g][b];
        }
        __syncthreads();

        if (kh == 0) {
            // combine halves, gates, h update
#pragma unroll
            for (int b = 0; b < BM; b++) {
                ull pr = red[(0 * BM + b) * 256 + c];
                ull pz = red[(1 * BM + b) * 256 + c];
                ull pg = red[(2 * BM + b) * 256 + c];
                float r  = sigm(hsum2(add2(acc[0][b], pr)) + br);
                float z  = sigm(hsum2(add2(acc[1][b], pz)) + bz);
                float xn = hsum2(acc[2][b]) + bxn;
                float hg = hsum2(pg) + bhg;
                float n  = tanh_(xn + r * hg);
                float hnew = z * (hreg[b] - n) + n;   // (1-z)n + z h
                hreg[b] = hnew;
                xh[b * K2 + Isz + c] = hnew;
                if (t + 1 == L[b]) hn[b] = hnew;
            }
        } else {
            // stage x_{t+1}
            if (t + 1 < Tsz) {
#pragma unroll
                for (int b = 0; b < BM; b++)
                    xh[b * K2 + c] = xvn[b];
            }
        }
        __syncthreads();
    }

    if (kh == 0) {
#pragma unroll
        for (int b = 0; b < BM; b++)
            out[(size_t)(b0 + b) * Hsz + c] = hn[b];  // L==0 rows stay 0
    }
}

extern "C" void kernel_launch(void* const* d_in, const int* in_sizes, int n_in,
                              void* d_out, int out_size) {
    const float* x      = (const float*)d_in[0];  // [B,T,I]
    const int*   seqlen = (const int*)d_in[1];    // [B]
    const float* W_ih   = (const float*)d_in[2];  // [3H,I]
    const float* W_hh   = (const float*)d_in[3];  // [3H,H]
    const float* b_ih   = (const float*)d_in[4];  // [3H]
    const float* b_hh   = (const float*)d_in[5];  // [3H]
    float*       out    = (float*)d_out;          // [B,H]

    static bool attr_set = false;
    if (!attr_set) {
        cudaFuncSetAttribute(gru_kernel, cudaFuncAttributeMaxDynamicSharedMemorySize,
                             SMEM_BYTES);
        attr_set = true;
    }
    prep_kernel<<<(NQ * Gsz * 4 + 255) / 256, 256>>>(W_ih, W_hh, b_ih, b_hh);
    gru_kernel<<<Bsz / BM, 512, SMEM_BYTES>>>(x, seqlen, out);
}

// round 10
// speedup vs baseline: 2.9423x; 1.4419x over previous
#include <cuda_runtime.h>
#include <cuda_fp16.h>
#include <cstdint>

// B=1024, T=512, I=H=256, 3H=768
#define Bsz 1024
#define Tsz 512
#define MGN 8      // batch groups (128 rows)
#define UGN 8      // unit groups (32 units -> 96 gate rows, gate-blocked r|z|n)

// ---------------- device scratch (static) ----------------
__device__ float g_xi[(size_t)Bsz * Tsz * 768];              // xi (no bias), col = ug*96+gate*32+u
__device__ __align__(16) __half g_W[2][UGN][2][96 * 256];    // [mat][ug][hi/lo][j*256+k]
// h exchange, double buffered: row = 512 halves: [0..255]=h_hi units, [256..511]=h_lo units
__device__ __align__(16) __half g_hx[2][(size_t)Bsz * 512];
__device__ int   g_flag[Tsz][MGN];
__device__ float g_bias[1024];  // [0]=br(ih+hh) [256]=bz(ih+hh) [512]=b_ih_n [768]=b_hh_n

// ---------------- SMEM layouts (bytes) ----------------
#define AROW  528                 // 264 halves per row (pad)
// gru_rec: A(67584) | W 2 passes (101376) | hstage(16384)
#define OFF_W   67584
#define WPASS   50688
#define OFF_HST 168960
#define SMEM_REC (OFF_HST + 16384)
// xproj: A_hi(67584) | A_lo(67584) | W 1 pass (50688)
#define OFF_A2  67584
#define OFF_WX  135168
#define SMEM_XP (OFF_WX + WPASS)
#define SMEM_BYTES (SMEM_XP > SMEM_REC ? SMEM_XP : SMEM_REC)

// ---------------- helpers ----------------
__device__ __forceinline__ uint32_t smem_u32(const void* p) {
    uint32_t a;
    asm("{ .reg .u64 t; cvta.to.shared.u64 t, %1; cvt.u32.u64 %0, t; }" : "=r"(a) : "l"(p));
    return a;
}
__device__ __forceinline__ void ldsm4(uint32_t* r, uint32_t a) {
    asm volatile("ldmatrix.sync.aligned.m8n8.x4.shared.b16 {%0,%1,%2,%3}, [%4];"
                 : "=r"(r[0]), "=r"(r[1]), "=r"(r[2]), "=r"(r[3]) : "r"(a));
}
__device__ __forceinline__ void mma16816(float* d, const uint32_t* a, const uint32_t* b) {
    asm volatile("mma.sync.aligned.m16n8k16.row.col.f32.f16.f16.f32 "
                 "{%0,%1,%2,%3}, {%4,%5,%6,%7}, {%8,%9}, {%0,%1,%2,%3};"
                 : "+f"(d[0]), "+f"(d[1]), "+f"(d[2]), "+f"(d[3])
                 : "r"(a[0]), "r"(a[1]), "r"(a[2]), "r"(a[3]), "r"(b[0]), "r"(b[1]));
}
__device__ __forceinline__ float sigm(float a)  { return 1.0f / (1.0f + __expf(-a)); }
__device__ __forceinline__ float tanh_(float a) { return 1.0f - 2.0f / (1.0f + __expf(2.0f * a)); }
__device__ __forceinline__ uint32_t h2u(__half2 h) { return *reinterpret_cast<uint32_t*>(&h); }

// One K=256 pass: acc[mt][g][j][4] += A(warp's 32 rows) @ W_pass^T.
// W stored [n][k] row-major == col-major B: NON-trans ldmatrix; bj0={r0,r2}, bj1={r1,r3}.
__device__ __forceinline__ void gemm_pass(uint32_t sAb, uint32_t sWb, int wm, int wn, int lane,
                                          float acc[2][3][2][4]) {
    const int l16 = lane & 15, h16 = (lane >> 4) & 1;
    const uint32_t aBase = sAb + (32 * wm + l16) * AROW + h16 * 16;
    const uint32_t bBase = sWb + (wn * 16 + l16) * AROW + h16 * 16;
#pragma unroll 4
    for (int kc = 0; kc < 16; kc++) {
        uint32_t a[2][4];
        ldsm4(a[0], aBase + kc * 32);
        ldsm4(a[1], aBase + 16 * AROW + kc * 32);
#pragma unroll
        for (int g = 0; g < 3; g++) {
            uint32_t b[4];
            ldsm4(b, bBase + g * 32 * AROW + kc * 32);
            uint32_t bj0[2] = {b[0], b[2]}, bj1[2] = {b[1], b[3]};
#pragma unroll
            for (int mt = 0; mt < 2; mt++) {
                mma16816(acc[mt][g][0], a[mt], bj0);
                mma16816(acc[mt][g][1], a[mt], bj1);
            }
        }
    }
}

// ---------------- prep ----------------
__global__ void prep_kernel(const float* __restrict__ W_ih, const float* __restrict__ W_hh,
                            const float* __restrict__ b_ih, const float* __restrict__ b_hh) {
    int idx = blockIdx.x * 256 + threadIdx.x;
    if (idx < 2 * UGN * 96 * 256) {
        int k = idx & 255, rest = idx >> 8;
        int j = rest % 96, ug = (rest / 96) & 7, m = rest / 768;
        int gate = j >> 5, u = j & 31;
        int orig = gate * 256 + ug * 32 + u;
        float wv = m ? W_hh[orig * 256 + k] : W_ih[orig * 256 + k];
        __half hi = __float2half_rn(wv);
        __half lo = __float2half_rn(wv - __half2float(hi));
        g_W[m][ug][0][j * 256 + k] = hi;
        g_W[m][ug][1][j * 256 + k] = lo;
    }
    if (idx < 256) {
        g_bias[idx]       = b_ih[idx]       + b_hh[idx];
        g_bias[256 + idx] = b_ih[256 + idx] + b_hh[256 + idx];
        g_bias[512 + idx] = b_ih[512 + idx];
        g_bias[768 + idx] = b_hh[512 + idx];
    }
    if (idx < Tsz * MGN) ((int*)g_flag)[idx] = 0;
}

// ---------------- phase A: xi = x @ W_ih^T (gate-blocked, hi/lo exact) ----------------
__global__ void __launch_bounds__(256, 1) xproj_kernel(const float* __restrict__ x) {
    extern __shared__ __align__(16) char sp[];
    const uint32_t sA = smem_u32(sp);
    const int tid = threadIdx.x, lane = tid & 31, w = tid >> 5;
    const int wm = w & 3, wn = w >> 2;
    const size_t bt0 = (size_t)blockIdx.x * 128;

    // x tile -> fp16 hi/lo A tiles (rows = 128 consecutive (b,t))
    const float4* x4 = (const float4*)(x + bt0 * 256);
    for (int i = tid; i < 8192; i += 256) {
        int row = i >> 6, c4 = i & 63;
        float4 v = __ldg(&x4[(size_t)row * 64 + c4]);
        __half h0 = __float2half_rn(v.x), h1 = __float2half_rn(v.y);
        __half h2 = __float2half_rn(v.z), h3 = __float2half_rn(v.w);
        __half l0 = __float2half_rn(v.x - __half2float(h0));
        __half l1 = __float2half_rn(v.y - __half2float(h1));
        __half l2 = __float2half_rn(v.z - __half2float(h2));
        __half l3 = __float2half_rn(v.w - __half2float(h3));
        uint2 hv = {h2u(__halves2half2(h0, h1)), h2u(__halves2half2(h2, h3))};
        uint2 lv = {h2u(__halves2half2(l0, l1)), h2u(__halves2half2(l2, l3))};
        *(uint2*)(sp + row * AROW + c4 * 8) = hv;
        *(uint2*)(sp + OFF_A2 + row * AROW + c4 * 8) = lv;
    }

#pragma unroll 1
    for (int ug = 0; ug < UGN; ug++) {
        float acc[2][3][2][4];
#pragma unroll
        for (int mt = 0; mt < 2; mt++)
#pragma unroll
            for (int g = 0; g < 3; g++)
#pragma unroll
                for (int j = 0; j < 2; j++)
#pragma unroll
                    for (int e = 0; e < 4; e++) acc[mt][g][j][e] = 0.0f;

#pragma unroll 1
        for (int p = 0; p < 2; p++) {
            __syncthreads();  // A staged / previous gemm reads of W done
            for (int i = tid; i < 3072; i += 256) {
                int j = i >> 5, q = i & 31;
                *(uint4*)(sp + OFF_WX + j * AROW + q * 16) =
                    ((const uint4*)&g_W[0][ug][p][0])[j * 32 + q];
            }
            __syncthreads();
            gemm_pass(sA, sA + OFF_WX, wm, wn, lane, acc);           // W_p @ x_hi
            if (p == 0)
                gemm_pass(sA + OFF_A2, sA + OFF_WX, wm, wn, lane, acc);  // W_hi @ x_lo
        }

#pragma unroll
        for (int mt = 0; mt < 2; mt++)
#pragma unroll
            for (int eh = 0; eh < 2; eh++) {
                int rl = 32 * wm + 16 * mt + (lane >> 2) + 8 * eh;
                float* go = g_xi + (bt0 + rl) * 768 + ug * 96 + wn * 16 + 2 * (lane & 3);
#pragma unroll
                for (int g = 0; g < 3; g++)
#pragma unroll
                    for (int j = 0; j < 2; j++) {
                        float2 v = {acc[mt][g][j][eh * 2], acc[mt][g][j][eh * 2 + 1]};
                        *(float2*)(go + g * 32 + j * 8) = v;
                    }
            }
    }
}

// ---------------- recurrence: 64 persistent CTAs ----------------
__global__ void __launch_bounds__(256, 1) gru_rec(const int* __restrict__ seqlen,
                                                  float* __restrict__ out) {
    extern __shared__ __align__(16) char sp[];
    const uint32_t sA = smem_u32(sp);
    const int tid = threadIdx.x, lane = tid & 31, w = tid >> 5;
    const int wm = w & 3, wn = w >> 2;
    const int bg = blockIdx.x >> 3, ug = blockIdx.x & 7;

    // W_hh hi/lo resident all steps
    for (int i = tid; i < 6144; i += 256) {
        int p = i / 3072, r2 = i - p * 3072, j = r2 >> 5, q = r2 & 31;
        *(uint4*)(sp + OFF_W + p * WPASS + j * AROW + q * 16) =
            ((const uint4*)&g_W[1][ug][p][0])[j * 32 + q];
    }
    // A = 0 (h0)
    {
        uint4 z = {0, 0, 0, 0};
        for (int i = tid; i < 4224; i += 256) ((uint4*)sp)[i] = z;
    }

    float br[4], bz[4], bxn[4], bhg[4];
#pragma unroll
    for (int j = 0; j < 2; j++)
#pragma unroll
        for (int e1 = 0; e1 < 2; e1++) {
            int u = j * 2 + e1;
            int hu = ug * 32 + 16 * wn + 8 * j + 2 * (lane & 3) + e1;
            br[u] = g_bias[hu]; bz[u] = g_bias[256 + hu];
            bxn[u] = g_bias[512 + hu]; bhg[u] = g_bias[768 + hu];
        }
    int Lr[4];
#pragma unroll
    for (int mt = 0; mt < 2; mt++)
#pragma unroll
        for (int eh = 0; eh < 2; eh++)
            Lr[mt * 2 + eh] = seqlen[bg * 128 + 32 * wm + 16 * mt + (lane >> 2) + 8 * eh];

    float hold[16], hn[16];
#pragma unroll
    for (int i = 0; i < 16; i++) { hold[i] = 0.0f; hn[i] = 0.0f; }
    __syncthreads();

#pragma unroll 1
    for (int t = 0; t < Tsz; t++) {
        const uint4* hr = (const uint4*)(g_hx[(t - 1) & 1] + (size_t)(bg * 128) * 512);
        if (t > 0) {
            const int* fp = &g_flag[t - 1][bg];
            int v;
            do { asm volatile("ld.global.acquire.gpu.b32 %0, [%1];" : "=r"(v) : "l"(fp)); }
            while (v < UGN);
            // stage h_hi (row stride = 64 uint4 = 512 halves; hi half = q 0..31)
            for (int i = tid; i < 4096; i += 256) {
                int row = i >> 5, q = i & 31;
                *(uint4*)(sp + row * AROW + q * 16) = hr[(size_t)row * 64 + q];
            }
        }
        __syncthreads();

        // xi preload (overlaps MMA scoreboard)
        float2 xif[2][2][3][2];
#pragma unroll
        for (int mt = 0; mt < 2; mt++)
#pragma unroll
            for (int eh = 0; eh < 2; eh++) {
                int rl = 32 * wm + 16 * mt + (lane >> 2) + 8 * eh;
                const float* xb = g_xi + ((size_t)(bg * 128 + rl) * Tsz + t) * 768 +
                                  ug * 96 + wn * 16 + 2 * (lane & 3);
#pragma unroll
                for (int g = 0; g < 3; g++)
#pragma unroll
                    for (int j = 0; j < 2; j++)
                        xif[mt][eh][g][j] = __ldg((const float2*)(xb + g * 32 + j * 8));
            }

        float acc[2][3][2][4];
#pragma unroll
        for (int mt = 0; mt < 2; mt++)
#pragma unroll
            for (int g = 0; g < 3; g++)
#pragma unroll
                for (int j = 0; j < 2; j++)
#pragma unroll
                    for (int e = 0; e < 4; e++) acc[mt][g][j][e] = 0.0f;

        gemm_pass(sA, sA + OFF_W,         wm, wn, lane, acc);  // W_hi @ h_hi
        gemm_pass(sA, sA + OFF_W + WPASS, wm, wn, lane, acc);  // W_lo @ h_hi
        __syncthreads();  // all reads of A done before restage
        if (t > 0) {
            for (int i = tid; i < 4096; i += 256) {
                int row = i >> 5, q = i & 31;
                *(uint4*)(sp + row * AROW + q * 16) = hr[(size_t)row * 64 + 32 + q];  // h_lo
            }
        }
        __syncthreads();
        gemm_pass(sA, sA + OFF_W, wm, wn, lane, acc);          // W_hi @ h_lo

        // epilogue: gates + h update; write hi/lo to hstage
#pragma unroll
        for (int mt = 0; mt < 2; mt++)
#pragma unroll
            for (int eh = 0; eh < 2; eh++)
#pragma unroll
                for (int j = 0; j < 2; j++)
#pragma unroll
                    for (int e1 = 0; e1 < 2; e1++) {
                        int e = eh * 2 + e1, u = j * 2 + e1;
                        int s = ((mt * 2 + eh) * 2 + j) * 2 + e1;
                        float xr = e1 ? xif[mt][eh][0][j].y : xif[mt][eh][0][j].x;
                        float xz = e1 ? xif[mt][eh][1][j].y : xif[mt][eh][1][j].x;
                        float xn = e1 ? xif[mt][eh][2][j].y : xif[mt][eh][2][j].x;
                        float rr = sigm(acc[mt][0][j][e] + xr + br[u]);
                        float zz = sigm(acc[mt][1][j][e] + xz + bz[u]);
                        float nn = tanh_(xn + bxn[u] + rr * (acc[mt][2][j][e] + bhg[u]));
                        float hv = zz * (hold[s] - nn) + nn;
                        hold[s] = hv;
                        if (t + 1 == Lr[mt * 2 + eh]) hn[s] = hv;
                        int rl = 32 * wm + 16 * mt + (lane >> 2) + 8 * eh;
                        int uig = 16 * wn + 8 * j + 2 * (lane & 3) + e1;
                        __half hh = __float2half_rn(hv);
                        __half hl = __float2half_rn(hv - __half2float(hh));
                        *(__half*)(sp + OFF_HST + (rl * 64 + uig) * 2) = hh;
                        *(__half*)(sp + OFF_HST + (rl * 64 + 32 + uig) * 2) = hl;
                    }
        __syncthreads();  // hstage complete; all gemm3 A-reads done

        // publish hi+lo (row = 512 halves in g_hx; hstage row = 64 halves)
        {
            __half* hd = g_hx[t & 1] + (size_t)(bg * 128) * 512;
            for (int i = tid; i < 1024; i += 256) {
                int row = i >> 3, s2 = i & 7, half = s2 >> 2, q = s2 & 3;
                *(uint4*)(hd + (size_t)row * 512 + half * 256 + ug * 32 + q * 8) =
                    ((const uint4*)(sp + OFF_HST + row * 128 + half * 64))[q];
            }
        }
        __threadfence();
        __syncthreads();
        if (tid == 0) atomicAdd(&g_flag[t][bg], 1);
    }

#pragma unroll
    for (int mt = 0; mt < 2; mt++)
#pragma unroll
        for (int eh = 0; eh < 2; eh++)
#pragma unroll
            for (int j = 0; j < 2; j++)
#pragma unroll
                for (int e1 = 0; e1 < 2; e1++) {
                    int s = ((mt * 2 + eh) * 2 + j) * 2 + e1;
                    int rl = 32 * wm + 16 * mt + (lane >> 2) + 8 * eh;
                    int uig = 16 * wn + 8 * j + 2 * (lane & 3) + e1;
                    out[(size_t)(bg * 128 + rl) * 256 + ug * 32 + uig] = hn[s];
                }
}

extern "C" void kernel_launch(void* const* d_in, const int* in_sizes, int n_in,
                              void* d_out, int out_size) {
    const float* x      = (const float*)d_in[0];
    const int*   seqlen = (const int*)d_in[1];
    const float* W_ih   = (const float*)d_in[2];
    const float* W_hh   = (const float*)d_in[3];
    const float* b_ih   = (const float*)d_in[4];
    const float* b_hh   = (const float*)d_in[5];
    float*       out    = (float*)d_out;

    static bool init = false;
    if (!init) {
        cudaFuncSetAttribute(xproj_kernel, cudaFuncAttributeMaxDynamicSharedMemorySize, SMEM_BYTES);
        cudaFuncSetAttribute(gru_rec, cudaFuncAttributeMaxDynamicSharedMemorySize, SMEM_BYTES);
        init = true;
    }
    prep_kernel<<<1536, 256>>>(W_ih, W_hh, b_ih, b_hh);
    xproj_kernel<<<(Bsz * Tsz) / 128, 256, SMEM_BYTES>>>(x);
    gru_rec<<<MGN * UGN, 256, SMEM_BYTES>>>(seqlen, out);
}

// round 11
// speedup vs baseline: 4.5408x; 1.5433x over previous
#include <cuda_runtime.h>
#include <cuda_fp16.h>
#include <cstdint>

// B=1024, T=512, I=H=256, 3H=768
#define Bsz 1024
#define Tsz 512
#define MGN 16     // batch groups (64 rows each)
#define UGN 8      // unit groups (32 units -> 96 gate rows, gate-blocked r|z|n)

// ---------------- device scratch (static) ----------------
__device__ float g_xi[(size_t)Bsz * Tsz * 768];              // xi (no bias), col = ug*96+gate*32+u
__device__ __align__(16) __half g_W[2][UGN][2][96 * 256];    // [mat][ug][hi/lo][j*256+k]
// h exchange, double buffered: row = 512 halves: [0..255]=h_hi units, [256..511]=h_lo units
__device__ __align__(16) __half g_hx[2][(size_t)Bsz * 512];
__device__ int   g_flag[Tsz][MGN];
__device__ float g_bias[1024];  // [0]=br(ih+hh) [256]=bz(ih+hh) [512]=b_ih_n [768]=b_hh_n

// ---------------- SMEM layouts (bytes) ----------------
#define AROW  528                 // 264 halves per row (pad)
// gru_rec: A_hi(64x528=33792) | A_lo(33792) | W 2 passes (101376) | hstage(8192)
#define OFF_ALO 33792
#define OFF_W   67584
#define WPASS   50688
#define OFF_HST 168960
#define SMEM_REC (OFF_HST + 8192)
// xproj: A_hi(128x528=67584) | A_lo(67584) | W 1 pass (50688)
#define OFF_A2  67584
#define OFF_WX  135168
#define SMEM_XP (OFF_WX + WPASS)

// ---------------- helpers ----------------
__device__ __forceinline__ uint32_t smem_u32(const void* p) {
    uint32_t a;
    asm("{ .reg .u64 t; cvta.to.shared.u64 t, %1; cvt.u32.u64 %0, t; }" : "=r"(a) : "l"(p));
    return a;
}
__device__ __forceinline__ void ldsm4(uint32_t* r, uint32_t a) {
    asm volatile("ldmatrix.sync.aligned.m8n8.x4.shared.b16 {%0,%1,%2,%3}, [%4];"
                 : "=r"(r[0]), "=r"(r[1]), "=r"(r[2]), "=r"(r[3]) : "r"(a));
}
__device__ __forceinline__ void mma16816(float* d, const uint32_t* a, const uint32_t* b) {
    asm volatile("mma.sync.aligned.m16n8k16.row.col.f32.f16.f16.f32 "
                 "{%0,%1,%2,%3}, {%4,%5,%6,%7}, {%8,%9}, {%0,%1,%2,%3};"
                 : "+f"(d[0]), "+f"(d[1]), "+f"(d[2]), "+f"(d[3])
                 : "r"(a[0]), "r"(a[1]), "r"(a[2]), "r"(a[3]), "r"(b[0]), "r"(b[1]));
}
__device__ __forceinline__ float sigm(float a)  { return 1.0f / (1.0f + __expf(-a)); }
__device__ __forceinline__ float tanh_(float a) { return 1.0f - 2.0f / (1.0f + __expf(2.0f * a)); }
__device__ __forceinline__ uint32_t h2u(__half2 h) { return *reinterpret_cast<uint32_t*>(&h); }

// K=256 pass, M=32 rows per warp (mt=2 tiles of 16) — used by xproj (M=128, warps 4wm x 2wn)
__device__ __forceinline__ void gemm2(uint32_t sAb, uint32_t sWb, int wm, int wn, int lane,
                                      float acc[2][3][2][4]) {
    const int l16 = lane & 15, h16 = (lane >> 4) & 1;
    const uint32_t aBase = sAb + (32 * wm + l16) * AROW + h16 * 16;
    const uint32_t bBase = sWb + (wn * 16 + l16) * AROW + h16 * 16;
#pragma unroll 4
    for (int kc = 0; kc < 16; kc++) {
        uint32_t a[2][4];
        ldsm4(a[0], aBase + kc * 32);
        ldsm4(a[1], aBase + 16 * AROW + kc * 32);
#pragma unroll
        for (int g = 0; g < 3; g++) {
            uint32_t b[4];
            ldsm4(b, bBase + g * 32 * AROW + kc * 32);
            uint32_t bj0[2] = {b[0], b[2]}, bj1[2] = {b[1], b[3]};
#pragma unroll
            for (int mt = 0; mt < 2; mt++) {
                mma16816(acc[mt][g][0], a[mt], bj0);
                mma16816(acc[mt][g][1], a[mt], bj1);
            }
        }
    }
}

// K=256 pass, M=16 rows per warp — used by gru_rec (M=64, warps 4wm x 2wn)
__device__ __forceinline__ void gemm1(uint32_t sAb, uint32_t sWb, int wm, int wn, int lane,
                                      float acc[3][2][4]) {
    const int l16 = lane & 15, h16 = (lane >> 4) & 1;
    const uint32_t aBase = sAb + (16 * wm + l16) * AROW + h16 * 16;
    const uint32_t bBase = sWb + (wn * 16 + l16) * AROW + h16 * 16;
#pragma unroll 4
    for (int kc = 0; kc < 16; kc++) {
        uint32_t a[4];
        ldsm4(a, aBase + kc * 32);
#pragma unroll
        for (int g = 0; g < 3; g++) {
            uint32_t b[4];
            ldsm4(b, bBase + g * 32 * AROW + kc * 32);
            uint32_t bj0[2] = {b[0], b[2]}, bj1[2] = {b[1], b[3]};
            mma16816(acc[g][0], a, bj0);
            mma16816(acc[g][1], a, bj1);
        }
    }
}

// ---------------- prep ----------------
__global__ void prep_kernel(const float* __restrict__ W_ih, const float* __restrict__ W_hh,
                            const float* __restrict__ b_ih, const float* __restrict__ b_hh) {
    int idx = blockIdx.x * 256 + threadIdx.x;
    if (idx < 2 * UGN * 96 * 256) {
        int k = idx & 255, rest = idx >> 8;
        int j = rest % 96, ug = (rest / 96) & 7, m = rest / 768;
        int gate = j >> 5, u = j & 31;
        int orig = gate * 256 + ug * 32 + u;
        float wv = m ? W_hh[orig * 256 + k] : W_ih[orig * 256 + k];
        __half hi = __float2half_rn(wv);
        __half lo = __float2half_rn(wv - __half2float(hi));
        g_W[m][ug][0][j * 256 + k] = hi;
        g_W[m][ug][1][j * 256 + k] = lo;
    }
    if (idx < 256) {
        g_bias[idx]       = b_ih[idx]       + b_hh[idx];
        g_bias[256 + idx] = b_ih[256 + idx] + b_hh[256 + idx];
        g_bias[512 + idx] = b_ih[512 + idx];
        g_bias[768 + idx] = b_hh[512 + idx];
    }
    if (idx < Tsz * MGN) ((int*)g_flag)[idx] = 0;
}

// ---------------- phase A: xi = x @ W_ih^T (gate-blocked, hi/lo exact) ----------------
__global__ void __launch_bounds__(256, 1) xproj_kernel(const float* __restrict__ x) {
    extern __shared__ __align__(16) char sp[];
    const uint32_t sA = smem_u32(sp);
    const int tid = threadIdx.x, lane = tid & 31, w = tid >> 5;
    const int wm = w & 3, wn = w >> 2;
    const size_t bt0 = (size_t)blockIdx.x * 128;

    // x tile -> fp16 hi/lo A tiles (rows = 128 consecutive (b,t))
    const float4* x4 = (const float4*)(x + bt0 * 256);
    for (int i = tid; i < 8192; i += 256) {
        int row = i >> 6, c4 = i & 63;
        float4 v = __ldg(&x4[(size_t)row * 64 + c4]);
        __half h0 = __float2half_rn(v.x), h1 = __float2half_rn(v.y);
        __half h2 = __float2half_rn(v.z), h3 = __float2half_rn(v.w);
        __half l0 = __float2half_rn(v.x - __half2float(h0));
        __half l1 = __float2half_rn(v.y - __half2float(h1));
        __half l2 = __float2half_rn(v.z - __half2float(h2));
        __half l3 = __float2half_rn(v.w - __half2float(h3));
        uint2 hv = {h2u(__halves2half2(h0, h1)), h2u(__halves2half2(h2, h3))};
        uint2 lv = {h2u(__halves2half2(l0, l1)), h2u(__halves2half2(l2, l3))};
        *(uint2*)(sp + row * AROW + c4 * 8) = hv;
        *(uint2*)(sp + OFF_A2 + row * AROW + c4 * 8) = lv;
    }

#pragma unroll 1
    for (int ug = 0; ug < UGN; ug++) {
        float acc[2][3][2][4];
#pragma unroll
        for (int mt = 0; mt < 2; mt++)
#pragma unroll
            for (int g = 0; g < 3; g++)
#pragma unroll
                for (int j = 0; j < 2; j++)
#pragma unroll
                    for (int e = 0; e < 4; e++) acc[mt][g][j][e] = 0.0f;

#pragma unroll 1
        for (int p = 0; p < 2; p++) {
            __syncthreads();  // A staged / previous gemm reads of W done
            for (int i = tid; i < 3072; i += 256) {
                int j = i >> 5, q = i & 31;
                *(uint4*)(sp + OFF_WX + j * AROW + q * 16) =
                    ((const uint4*)&g_W[0][ug][p][0])[j * 32 + q];
            }
            __syncthreads();
            gemm2(sA, sA + OFF_WX, wm, wn, lane, acc);               // W_p @ x_hi
            if (p == 0)
                gemm2(sA + OFF_A2, sA + OFF_WX, wm, wn, lane, acc);  // W_hi @ x_lo
        }

#pragma unroll
        for (int mt = 0; mt < 2; mt++)
#pragma unroll
            for (int eh = 0; eh < 2; eh++) {
                int rl = 32 * wm + 16 * mt + (lane >> 2) + 8 * eh;
                float* go = g_xi + (bt0 + rl) * 768 + ug * 96 + wn * 16 + 2 * (lane & 3);
#pragma unroll
                for (int g = 0; g < 3; g++)
#pragma unroll
                    for (int j = 0; j < 2; j++) {
                        float2 v = {acc[mt][g][j][eh * 2], acc[mt][g][j][eh * 2 + 1]};
                        *(float2*)(go + g * 32 + j * 8) = v;
                    }
            }
    }
}

// ---------------- recurrence: 128 persistent CTAs (M=64 per CTA) ----------------
__global__ void __launch_bounds__(256, 1) gru_rec(const int* __restrict__ seqlen,
                                                  float* __restrict__ out) {
    extern __shared__ __align__(16) char sp[];
    const uint32_t sA = smem_u32(sp);
    const int tid = threadIdx.x, lane = tid & 31, w = tid >> 5;
    const int wm = w & 3, wn = w >> 2;
    const int bg = blockIdx.x >> 3, ug = blockIdx.x & 7;

    // W_hh hi/lo resident all steps
    for (int i = tid; i < 6144; i += 256) {
        int p = i / 3072, r2 = i - p * 3072, j = r2 >> 5, q = r2 & 31;
        *(uint4*)(sp + OFF_W + p * WPASS + j * AROW + q * 16) =
            ((const uint4*)&g_W[1][ug][p][0])[j * 32 + q];
    }
    // A_hi = A_lo = 0 (h0)
    {
        uint4 z = {0, 0, 0, 0};
        for (int i = tid; i < 4224; i += 256) ((uint4*)sp)[i] = z;
    }

    float br[4], bz[4], bxn[4], bhg[4];
#pragma unroll
    for (int j = 0; j < 2; j++)
#pragma unroll
        for (int e1 = 0; e1 < 2; e1++) {
            int u = j * 2 + e1;
            int hu = ug * 32 + 16 * wn + 8 * j + 2 * (lane & 3) + e1;
            br[u] = g_bias[hu]; bz[u] = g_bias[256 + hu];
            bxn[u] = g_bias[512 + hu]; bhg[u] = g_bias[768 + hu];
        }
    int Lr[2];
#pragma unroll
    for (int eh = 0; eh < 2; eh++)
        Lr[eh] = seqlen[bg * 64 + 16 * wm + (lane >> 2) + 8 * eh];

    float hold[8], hn[8];
#pragma unroll
    for (int i = 0; i < 8; i++) { hold[i] = 0.0f; hn[i] = 0.0f; }
    __syncthreads();

#pragma unroll 1
    for (int t = 0; t < Tsz; t++) {
        // xi preload FIRST — its memory latency hides behind the flag wait
        float2 xif[2][3][2];
#pragma unroll
        for (int eh = 0; eh < 2; eh++) {
            int rl = 16 * wm + (lane >> 2) + 8 * eh;
            const float* xb = g_xi + ((size_t)(bg * 64 + rl) * Tsz + t) * 768 +
                              ug * 96 + wn * 16 + 2 * (lane & 3);
#pragma unroll
            for (int g = 0; g < 3; g++)
#pragma unroll
                for (int j = 0; j < 2; j++)
                    xif[eh][g][j] = __ldg((const float2*)(xb + g * 32 + j * 8));
        }

        if (t > 0) {
            const int* fp = &g_flag[t - 1][bg];
            int v;
            do { asm volatile("ld.global.acquire.gpu.b32 %0, [%1];" : "=r"(v) : "l"(fp)); }
            while (v < UGN);
            // stage h_hi -> A_hi and h_lo -> A_lo in one pass (g_hx row = 64 uint4)
            const uint4* hr = (const uint4*)(g_hx[(t - 1) & 1] + (size_t)(bg * 64) * 512);
            for (int i = tid; i < 4096; i += 256) {
                int row = i >> 6, rest = i & 63, half = rest >> 5, q = rest & 31;
                *(uint4*)(sp + half * OFF_ALO + row * AROW + q * 16) =
                    hr[(size_t)row * 64 + half * 32 + q];
            }
        }
        __syncthreads();

        float acc[3][2][4];
#pragma unroll
        for (int g = 0; g < 3; g++)
#pragma unroll
            for (int j = 0; j < 2; j++)
#pragma unroll
                for (int e = 0; e < 4; e++) acc[g][j][e] = 0.0f;

        gemm1(sA,           sA + OFF_W,         wm, wn, lane, acc);  // W_hi @ h_hi
        gemm1(sA,           sA + OFF_W + WPASS, wm, wn, lane, acc);  // W_lo @ h_hi
        gemm1(sA + OFF_ALO, sA + OFF_W,         wm, wn, lane, acc);  // W_hi @ h_lo

        // epilogue: gates + h update; stage hi/lo halves
#pragma unroll
        for (int eh = 0; eh < 2; eh++)
#pragma unroll
            for (int j = 0; j < 2; j++)
#pragma unroll
                for (int e1 = 0; e1 < 2; e1++) {
                    int e = eh * 2 + e1, u = j * 2 + e1;
                    int s = (eh * 2 + j) * 2 + e1;
                    float xr = e1 ? xif[eh][0][j].y : xif[eh][0][j].x;
                    float xz = e1 ? xif[eh][1][j].y : xif[eh][1][j].x;
                    float xn = e1 ? xif[eh][2][j].y : xif[eh][2][j].x;
                    float rr = sigm(acc[0][j][e] + xr + br[u]);
                    float zz = sigm(acc[1][j][e] + xz + bz[u]);
                    float nn = tanh_(xn + bxn[u] + rr * (acc[2][j][e] + bhg[u]));
                    float hv = zz * (hold[s] - nn) + nn;
                    hold[s] = hv;
                    if (t + 1 == Lr[eh]) hn[s] = hv;
                    int rl = 16 * wm + (lane >> 2) + 8 * eh;
                    int uig = 16 * wn + 8 * j + 2 * (lane & 3) + e1;
                    __half hh = __float2half_rn(hv);
                    __half hl = __float2half_rn(hv - __half2float(hh));
                    *(__half*)(sp + OFF_HST + (rl * 64 + uig) * 2) = hh;
                    *(__half*)(sp + OFF_HST + (rl * 64 + 32 + uig) * 2) = hl;
                }
        __syncthreads();  // hstage complete; all gemm A-reads done (safe to restage next t)

        // publish hi+lo (g_hx row = 512 halves; hstage row = 64 halves)
        {
            __half* hd = g_hx[t & 1] + (size_t)(bg * 64) * 512;
            for (int i = tid; i < 512; i += 256) {
                int row = i >> 3, s2 = i & 7, half = s2 >> 2, q = s2 & 3;
                *(uint4*)(hd + (size_t)row * 512 + half * 256 + ug * 32 + q * 8) =
                    ((const uint4*)(sp + OFF_HST + row * 128 + half * 64))[q];
            }
        }
        __threadfence();
        __syncthreads();
        if (tid == 0) atomicAdd(&g_flag[t][bg], 1);
    }

#pragma unroll
    for (int eh = 0; eh < 2; eh++)
#pragma unroll
        for (int j = 0; j < 2; j++)
#pragma unroll
            for (int e1 = 0; e1 < 2; e1++) {
                int s = (eh * 2 + j) * 2 + e1;
                int rl = 16 * wm + (lane >> 2) + 8 * eh;
                int uig = 16 * wn + 8 * j + 2 * (lane & 3) + e1;
                out[(size_t)(bg * 64 + rl) * 256 + ug * 32 + uig] = hn[s];
            }
}

extern "C" void kernel_launch(void* const* d_in, const int* in_sizes, int n_in,
                              void* d_out, int out_size) {
    const float* x      = (const float*)d_in[0];
    const int*   seqlen = (const int*)d_in[1];
    const float* W_ih   = (const float*)d_in[2];
    const float* W_hh   = (const float*)d_in[3];
    const float* b_ih   = (const float*)d_in[4];
    const float* b_hh   = (const float*)d_in[5];
    float*       out    = (float*)d_out;

    static bool init = false;
    if (!init) {
        cudaFuncSetAttribute(xproj_kernel, cudaFuncAttributeMaxDynamicSharedMemorySize, SMEM_XP);
        cudaFuncSetAttribute(gru_rec, cudaFuncAttributeMaxDynamicSharedMemorySize, SMEM_REC);
        init = true;
    }
    prep_kernel<<<1536, 256>>>(W_ih, W_hh, b_ih, b_hh);
    xproj_kernel<<<(Bsz * Tsz) / 128, 256, SMEM_XP>>>(x);
    gru_rec<<<MGN * UGN, 256, SMEM_REC>>>(seqlen, out);
}

// round 12
// speedup vs baseline: 5.2993x; 1.1670x over previous
#include <cuda_runtime.h>
#include <cuda_fp16.h>
#include <cstdint>

// B=1024, T=512, I=H=256, 3H=768
#define Bsz 1024
#define Tsz 512
#define MGN 16     // batch groups (64 rows each)
#define UGN 8      // unit groups (32 units -> 96 gate rows, gate-blocked r|z|n)

// ---------------- device scratch (static) ----------------
__device__ float g_xi[(size_t)Bsz * Tsz * 768];              // xi (no bias), col = ug*96+gate*32+u
__device__ __align__(16) __half g_W[2][UGN][2][96 * 256];    // [mat][ug][hi/lo][j*256+k]
// h exchange, double buffered: row = 512 halves: [0..255]=h_hi units, [256..511]=h_lo units
__device__ __align__(16) __half g_hx[2][(size_t)Bsz * 512];
__device__ int   g_flag[Tsz][MGN];
__device__ float g_bias[1024];  // [0]=br(ih+hh) [256]=bz(ih+hh) [512]=b_ih_n [768]=b_hh_n

// ---------------- SMEM layouts (bytes) ----------------
#define AROW  528                 // 264 halves per row (pad keeps ldsm phases conflict-free)
// gru_rec: A_hi(64x528=33792) | A_lo(33792) | W 2 passes (101376)
#define OFF_ALO 33792
#define OFF_W   67584
#define WPASS   50688
#define SMEM_REC (OFF_W + 2 * WPASS)
// xproj: A_hi(128x528=67584) | A_lo(67584) | W 1 pass (50688)
#define OFF_A2  67584
#define OFF_WX  135168
#define SMEM_XP (OFF_WX + WPASS)

// ---------------- helpers ----------------
__device__ __forceinline__ uint32_t smem_u32(const void* p) {
    uint32_t a;
    asm("{ .reg .u64 t; cvta.to.shared.u64 t, %1; cvt.u32.u64 %0, t; }" : "=r"(a) : "l"(p));
    return a;
}
__device__ __forceinline__ void ldsm4(uint32_t* r, uint32_t a) {
    asm volatile("ldmatrix.sync.aligned.m8n8.x4.shared.b16 {%0,%1,%2,%3}, [%4];"
                 : "=r"(r[0]), "=r"(r[1]), "=r"(r[2]), "=r"(r[3]) : "r"(a));
}
__device__ __forceinline__ void ldsm2(uint32_t* r, uint32_t a) {
    asm volatile("ldmatrix.sync.aligned.m8n8.x2.shared.b16 {%0,%1}, [%2];"
                 : "=r"(r[0]), "=r"(r[1]) : "r"(a));
}
__device__ __forceinline__ void mma16816(float* d, const uint32_t* a, const uint32_t* b) {
    asm volatile("mma.sync.aligned.m16n8k16.row.col.f32.f16.f16.f32 "
                 "{%0,%1,%2,%3}, {%4,%5,%6,%7}, {%8,%9}, {%0,%1,%2,%3};"
                 : "+f"(d[0]), "+f"(d[1]), "+f"(d[2]), "+f"(d[3])
                 : "r"(a[0]), "r"(a[1]), "r"(a[2]), "r"(a[3]), "r"(b[0]), "r"(b[1]));
}
__device__ __forceinline__ float sigm(float a)  { return 1.0f / (1.0f + __expf(-a)); }
__device__ __forceinline__ float tanh_(float a) { return 1.0f - 2.0f / (1.0f + __expf(2.0f * a)); }
__device__ __forceinline__ uint32_t h2u(__half2 h) { return *reinterpret_cast<uint32_t*>(&h); }

// K=256 pass, M=32 rows per warp (mt=2 tiles of 16) — used by xproj (M=128, warps 4wm x 2wn)
__device__ __forceinline__ void gemm2(uint32_t sAb, uint32_t sWb, int wm, int wn, int lane,
                                      float acc[2][3][2][4]) {
    const int l16 = lane & 15, h16 = (lane >> 4) & 1;
    const uint32_t aBase = sAb + (32 * wm + l16) * AROW + h16 * 16;
    const uint32_t bBase = sWb + (wn * 16 + l16) * AROW + h16 * 16;
#pragma unroll 4
    for (int kc = 0; kc < 16; kc++) {
        uint32_t a[2][4];
        ldsm4(a[0], aBase + kc * 32);
        ldsm4(a[1], aBase + 16 * AROW + kc * 32);
#pragma unroll
        for (int g = 0; g < 3; g++) {
            uint32_t b[4];
            ldsm4(b, bBase + g * 32 * AROW + kc * 32);
            uint32_t bj0[2] = {b[0], b[2]}, bj1[2] = {b[1], b[3]};
#pragma unroll
            for (int mt = 0; mt < 2; mt++) {
                mma16816(acc[mt][g][0], a[mt], bj0);
                mma16816(acc[mt][g][1], a[mt], bj1);
            }
        }
    }
}

// ---------------- prep ----------------
__global__ void prep_kernel(const float* __restrict__ W_ih, const float* __restrict__ W_hh,
                            const float* __restrict__ b_ih, const float* __restrict__ b_hh) {
    int idx = blockIdx.x * 256 + threadIdx.x;
    if (idx < 2 * UGN * 96 * 256) {
        int k = idx & 255, rest = idx >> 8;
        int j = rest % 96, ug = (rest / 96) & 7, m = rest / 768;
        int gate = j >> 5, u = j & 31;
        int orig = gate * 256 + ug * 32 + u;
        float wv = m ? W_hh[orig * 256 + k] : W_ih[orig * 256 + k];
        __half hi = __float2half_rn(wv);
        __half lo = __float2half_rn(wv - __half2float(hi));
        g_W[m][ug][0][j * 256 + k] = hi;
        g_W[m][ug][1][j * 256 + k] = lo;
    }
    if (idx < 256) {
        g_bias[idx]       = b_ih[idx]       + b_hh[idx];
        g_bias[256 + idx] = b_ih[256 + idx] + b_hh[256 + idx];
        g_bias[512 + idx] = b_ih[512 + idx];
        g_bias[768 + idx] = b_hh[512 + idx];
    }
    if (idx < Tsz * MGN) ((int*)g_flag)[idx] = 0;
}

// ---------------- phase A: xi = x @ W_ih^T (gate-blocked, hi/lo exact) ----------------
__global__ void __launch_bounds__(256, 1) xproj_kernel(const float* __restrict__ x) {
    extern __shared__ __align__(16) char sp[];
    const uint32_t sA = smem_u32(sp);
    const int tid = threadIdx.x, lane = tid & 31, w = tid >> 5;
    const int wm = w & 3, wn = w >> 2;
    const size_t bt0 = (size_t)blockIdx.x * 128;

    // x tile -> fp16 hi/lo A tiles (rows = 128 consecutive (b,t))
    const float4* x4 = (const float4*)(x + bt0 * 256);
    for (int i = tid; i < 8192; i += 256) {
        int row = i >> 6, c4 = i & 63;
        float4 v = __ldg(&x4[(size_t)row * 64 + c4]);
        __half h0 = __float2half_rn(v.x), h1 = __float2half_rn(v.y);
        __half h2 = __float2half_rn(v.z), h3 = __float2half_rn(v.w);
        __half l0 = __float2half_rn(v.x - __half2float(h0));
        __half l1 = __float2half_rn(v.y - __half2float(h1));
        __half l2 = __float2half_rn(v.z - __half2float(h2));
        __half l3 = __float2half_rn(v.w - __half2float(h3));
        uint2 hv = {h2u(__halves2half2(h0, h1)), h2u(__halves2half2(h2, h3))};
        uint2 lv = {h2u(__halves2half2(l0, l1)), h2u(__halves2half2(l2, l3))};
        *(uint2*)(sp + row * AROW + c4 * 8) = hv;
        *(uint2*)(sp + OFF_A2 + row * AROW + c4 * 8) = lv;
    }

#pragma unroll 1
    for (int ug = 0; ug < UGN; ug++) {
        float acc[2][3][2][4];
#pragma unroll
        for (int mt = 0; mt < 2; mt++)
#pragma unroll
            for (int g = 0; g < 3; g++)
#pragma unroll
                for (int j = 0; j < 2; j++)
#pragma unroll
                    for (int e = 0; e < 4; e++) acc[mt][g][j][e] = 0.0f;

#pragma unroll 1
        for (int p = 0; p < 2; p++) {
            __syncthreads();  // A staged / previous gemm reads of W done
            for (int i = tid; i < 3072; i += 256) {
                int j = i >> 5, q = i & 31;
                *(uint4*)(sp + OFF_WX + j * AROW + q * 16) =
                    ((const uint4*)&g_W[0][ug][p][0])[j * 32 + q];
            }
            __syncthreads();
            gemm2(sA, sA + OFF_WX, wm, wn, lane, acc);               // W_p @ x_hi
            if (p == 0)
                gemm2(sA + OFF_A2, sA + OFF_WX, wm, wn, lane, acc);  // W_hi @ x_lo
        }

#pragma unroll
        for (int mt = 0; mt < 2; mt++)
#pragma unroll
            for (int eh = 0; eh < 2; eh++) {
                int rl = 32 * wm + 16 * mt + (lane >> 2) + 8 * eh;
                float* go = g_xi + (bt0 + rl) * 768 + ug * 96 + wn * 16 + 2 * (lane & 3);
#pragma unroll
                for (int g = 0; g < 3; g++)
#pragma unroll
                    for (int j = 0; j < 2; j++) {
                        float2 v = {acc[mt][g][j][eh * 2], acc[mt][g][j][eh * 2 + 1]};
                        *(float2*)(go + g * 32 + j * 8) = v;
                    }
            }
    }
}

// ---------------- recurrence: 128 persistent CTAs, 512 threads (M=64, warp N=24) --------
__global__ void __launch_bounds__(512, 1) gru_rec(const int* __restrict__ seqlen,
                                                  float* __restrict__ out) {
    extern __shared__ __align__(16) char sp[];
    const uint32_t sA = smem_u32(sp);
    const int tid = threadIdx.x, lane = tid & 31, w = tid >> 5;
    const int wm = w & 3, wn = w >> 2;                 // wm: 16-row block, wn: 8-unit block
    const int l16 = lane & 15, h16 = (lane >> 4) & 1;
    const int bg = blockIdx.x >> 3, ug = blockIdx.x & 7;

    // W_hh hi/lo resident all steps
    for (int i = tid; i < 6144; i += 512) {
        int p = i / 3072, r2 = i - p * 3072, j = r2 >> 5, q = r2 & 31;
        *(uint4*)(sp + OFF_W + p * WPASS + j * AROW + q * 16) =
            ((const uint4*)&g_W[1][ug][p][0])[j * 32 + q];
    }
    // A_hi = A_lo = 0 (h0)
    {
        uint4 z = {0, 0, 0, 0};
        for (int i = tid; i < 4224; i += 512) ((uint4*)sp)[i] = z;
    }

    // thread-resident biases (2 units) and seqlen (2 rows)
    const int ucol = 8 * wn + 2 * (lane & 3);          // first of thread's 2 unit-cols
    float br[2], bz[2], bxn[2], bhg[2];
#pragma unroll
    for (int e1 = 0; e1 < 2; e1++) {
        int hu = ug * 32 + ucol + e1;
        br[e1] = g_bias[hu]; bz[e1] = g_bias[256 + hu];
        bxn[e1] = g_bias[512 + hu]; bhg[e1] = g_bias[768 + hu];
    }
    const int row0 = 16 * wm + (lane >> 2);
    int Lr[2];
    Lr[0] = seqlen[bg * 64 + row0];
    Lr[1] = seqlen[bg * 64 + row0 + 8];

    float hold[2][2], hn[2][2];
#pragma unroll
    for (int eh = 0; eh < 2; eh++)
#pragma unroll
        for (int e1 = 0; e1 < 2; e1++) { hold[eh][e1] = 0.0f; hn[eh][e1] = 0.0f; }
    __syncthreads();

    const uint32_t aHiBase = sA + (16 * wm + l16) * AROW + h16 * 16;
    const uint32_t aLoBase = aHiBase + OFF_ALO;
    const uint32_t bRow    = (8 * wn + (lane & 7)) * AROW + ((l16 >> 3) & 1) * 16;

#pragma unroll 1
    for (int t = 0; t < Tsz; t++) {
        // xi preload FIRST — memory latency hides behind the flag wait
        float2 xif[2][3];
#pragma unroll
        for (int eh = 0; eh < 2; eh++) {
            const float* xb = g_xi + ((size_t)(bg * 64 + row0 + 8 * eh) * Tsz + t) * 768 +
                              ug * 96 + ucol;
#pragma unroll
            for (int g = 0; g < 3; g++)
                xif[eh][g] = __ldg((const float2*)(xb + g * 32));
        }

        if (t > 0) {
            const int* fp = &g_flag[t - 1][bg];
            int v;
            do { asm volatile("ld.global.acquire.gpu.b32 %0, [%1];" : "=r"(v) : "l"(fp)); }
            while (v < UGN);
            // stage h_hi -> A_hi and h_lo -> A_lo (g_hx row = 64 uint4)
            const uint4* hr = (const uint4*)(g_hx[(t - 1) & 1] + (size_t)(bg * 64) * 512);
            for (int i = tid; i < 4096; i += 512) {
                int row = i >> 6, rest = i & 63, half = rest >> 5, q = rest & 31;
                *(uint4*)(sp + half * OFF_ALO + row * AROW + q * 16) =
                    hr[(size_t)row * 64 + half * 32 + q];
            }
        }
        __syncthreads();

        float acc[3][4];
#pragma unroll
        for (int g = 0; g < 3; g++)
#pragma unroll
            for (int e = 0; e < 4; e++) acc[g][e] = 0.0f;

        // merged 3-pass GEMM: per kc, per gate: {W_hi@h_hi, W_lo@h_hi, W_hi@h_lo}
#pragma unroll 4
        for (int kc = 0; kc < 16; kc++) {
            uint32_t ah[4], al[4];
            ldsm4(ah, aHiBase + kc * 32);
            ldsm4(al, aLoBase + kc * 32);
#pragma unroll
            for (int g = 0; g < 3; g++) {
                uint32_t bh[2], bl[2];
                uint32_t baddr = g * 32 * AROW + bRow + kc * 32;
                ldsm2(bh, sA + OFF_W + baddr);
                ldsm2(bl, sA + OFF_W + WPASS + baddr);
                mma16816(acc[g], ah, bh);
                mma16816(acc[g], ah, bl);
                mma16816(acc[g], al, bh);
            }
        }

        // epilogue: gates + h update; publish straight to g_hx
#pragma unroll
        for (int eh = 0; eh < 2; eh++) {
            float hv2[2];
#pragma unroll
            for (int e1 = 0; e1 < 2; e1++) {
                int e = 2 * eh + e1;
                float xr = e1 ? xif[eh][0].y : xif[eh][0].x;
                float xz = e1 ? xif[eh][1].y : xif[eh][1].x;
                float xn = e1 ? xif[eh][2].y : xif[eh][2].x;
                float rr = sigm(acc[0][e] + xr + br[e1]);
                float zz = sigm(acc[1][e] + xz + bz[e1]);
                float nn = tanh_(xn + bxn[e1] + rr * (acc[2][e] + bhg[e1]));
                float hv = zz * (hold[eh][e1] - nn) + nn;
                hold[eh][e1] = hv;
                if (t + 1 == Lr[eh]) hn[eh][e1] = hv;
                hv2[e1] = hv;
            }
            __half h0 = __float2half_rn(hv2[0]), h1 = __float2half_rn(hv2[1]);
            __half l0 = __float2half_rn(hv2[0] - __half2float(h0));
            __half l1 = __float2half_rn(hv2[1] - __half2float(h1));
            __half* hd = g_hx[t & 1] + (size_t)(bg * 64 + row0 + 8 * eh) * 512 + ug * 32 + ucol;
            *(uint32_t*)hd         = h2u(__halves2half2(h0, h1));
            *(uint32_t*)(hd + 256) = h2u(__halves2half2(l0, l1));
        }
        __threadfence();
        __syncthreads();   // publishes done + all A-tile reads done (safe to restage)
        if (tid == 0) atomicAdd(&g_flag[t][bg], 1);
    }

#pragma unroll
    for (int eh = 0; eh < 2; eh++)
#pragma unroll
        for (int e1 = 0; e1 < 2; e1++)
            out[(size_t)(bg * 64 + row0 + 8 * eh) * 256 + ug * 32 + ucol + e1] = hn[eh][e1];
}

extern "C" void kernel_launch(void* const* d_in, const int* in_sizes, int n_in,
                              void* d_out, int out_size) {
    const float* x      = (const float*)d_in[0];
    const int*   seqlen = (const int*)d_in[1];
    const float* W_ih   = (const float*)d_in[2];
    const float* W_hh   = (const float*)d_in[3];
    const float* b_ih   = (const float*)d_in[4];
    const float* b_hh   = (const float*)d_in[5];
    float*       out    = (float*)d_out;

    static bool init = false;
    if (!init) {
        cudaFuncSetAttribute(xproj_kernel, cudaFuncAttributeMaxDynamicSharedMemorySize, SMEM_XP);
        cudaFuncSetAttribute(gru_rec, cudaFuncAttributeMaxDynamicSharedMemorySize, SMEM_REC);
        init = true;
    }
    prep_kernel<<<1536, 256>>>(W_ih, W_hh, b_ih, b_hh);
    xproj_kernel<<<(Bsz * Tsz) / 128, 256, SMEM_XP>>>(x);
    gru_rec<<<MGN * UGN, 512, SMEM_REC>>>(seqlen, out);
}

// round 13
// speedup vs baseline: 5.6109x; 1.0588x over previous
#include <cuda_runtime.h>
#include <cuda_fp16.h>
#include <cstdint>

// B=1024, T=512, I=H=256, 3H=768
#define Bsz 1024
#define Tsz 512
#define MGN 16     // batch groups (64 rows each)
#define UGN 8      // unit groups (32 units -> 96 gate rows, gate-blocked r|z|n)

// ---------------- device scratch (static) ----------------
__device__ float g_xi[(size_t)Bsz * Tsz * 768];              // xi (no bias), col = ug*96+gate*32+u
__device__ __align__(16) __half g_W[2][UGN][2][96 * 256];    // [mat][ug][hi/lo][j*256+k]
// h exchange, double buffered: row = 512 halves: [0..255]=h_hi units, [256..511]=h_lo units
__device__ __align__(16) __half g_hx[2][(size_t)Bsz * 512];
__device__ int   g_flag[Tsz][MGN];
__device__ float g_bias[1024];  // [0]=br(ih+hh) [256]=bz(ih+hh) [512]=b_ih_n [768]=b_hh_n

// ---------------- SMEM layouts (bytes) ----------------
#define AROW  528                 // 264 halves per row (pad keeps ldsm phases conflict-free)
// gru_rec: A_hi(64x528=33792) | A_lo(33792) | W 2 passes (101376)
#define OFF_ALO 33792
#define OFF_W   67584
#define WPASS   50688
#define SMEM_REC (OFF_W + 2 * WPASS)
// xproj: A_hi(128x528=67584) | A_lo(67584) | W 1 pass (50688)
#define OFF_A2  67584
#define OFF_WX  135168
#define SMEM_XP (OFF_WX + WPASS)

// ---------------- helpers ----------------
__device__ __forceinline__ uint32_t smem_u32(const void* p) {
    uint32_t a;
    asm("{ .reg .u64 t; cvta.to.shared.u64 t, %1; cvt.u32.u64 %0, t; }" : "=r"(a) : "l"(p));
    return a;
}
__device__ __forceinline__ void ldsm4(uint32_t* r, uint32_t a) {
    asm volatile("ldmatrix.sync.aligned.m8n8.x4.shared.b16 {%0,%1,%2,%3}, [%4];"
                 : "=r"(r[0]), "=r"(r[1]), "=r"(r[2]), "=r"(r[3]) : "r"(a));
}
__device__ __forceinline__ void ldsm2(uint32_t* r, uint32_t a) {
    asm volatile("ldmatrix.sync.aligned.m8n8.x2.shared.b16 {%0,%1}, [%2];"
                 : "=r"(r[0]), "=r"(r[1]) : "r"(a));
}
__device__ __forceinline__ void mma16816(float* d, const uint32_t* a, const uint32_t* b) {
    asm volatile("mma.sync.aligned.m16n8k16.row.col.f32.f16.f16.f32 "
                 "{%0,%1,%2,%3}, {%4,%5,%6,%7}, {%8,%9}, {%0,%1,%2,%3};"
                 : "+f"(d[0]), "+f"(d[1]), "+f"(d[2]), "+f"(d[3])
                 : "r"(a[0]), "r"(a[1]), "r"(a[2]), "r"(a[3]), "r"(b[0]), "r"(b[1]));
}
__device__ __forceinline__ void cpasync16(uint32_t dst, const void* src) {
    asm volatile("cp.async.ca.shared.global [%0], [%1], 16;" :: "r"(dst), "l"(src));
}
__device__ __forceinline__ float sigm(float a)  {
    return __fdividef(1.0f, 1.0f + __expf(-a));
}
__device__ __forceinline__ float tanh_(float a) {
    return 1.0f - __fdividef(2.0f, 1.0f + __expf(2.0f * a));
}
__device__ __forceinline__ uint32_t h2u(__half2 h) { return *reinterpret_cast<uint32_t*>(&h); }

// K=256 pass, M=32 rows per warp (mt=2 tiles of 16) — used by xproj (M=128, warps 4wm x 2wn)
__device__ __forceinline__ void gemm2(uint32_t sAb, uint32_t sWb, int wm, int wn, int lane,
                                      float acc[2][3][2][4]) {
    const int l16 = lane & 15, h16 = (lane >> 4) & 1;
    const uint32_t aBase = sAb + (32 * wm + l16) * AROW + h16 * 16;
    const uint32_t bBase = sWb + (wn * 16 + l16) * AROW + h16 * 16;
#pragma unroll 4
    for (int kc = 0; kc < 16; kc++) {
        uint32_t a[2][4];
        ldsm4(a[0], aBase + kc * 32);
        ldsm4(a[1], aBase + 16 * AROW + kc * 32);
#pragma unroll
        for (int g = 0; g < 3; g++) {
            uint32_t b[4];
            ldsm4(b, bBase + g * 32 * AROW + kc * 32);
            uint32_t bj0[2] = {b[0], b[2]}, bj1[2] = {b[1], b[3]};
#pragma unroll
            for (int mt = 0; mt < 2; mt++) {
                mma16816(acc[mt][g][0], a[mt], bj0);
                mma16816(acc[mt][g][1], a[mt], bj1);
            }
        }
    }
}

// ---------------- prep ----------------
__global__ void prep_kernel(const float* __restrict__ W_ih, const float* __restrict__ W_hh,
                            const float* __restrict__ b_ih, const float* __restrict__ b_hh) {
    int idx = blockIdx.x * 256 + threadIdx.x;
    if (idx < 2 * UGN * 96 * 256) {
        int k = idx & 255, rest = idx >> 8;
        int j = rest % 96, ug = (rest / 96) & 7, m = rest / 768;
        int gate = j >> 5, u = j & 31;
        int orig = gate * 256 + ug * 32 + u;
        float wv = m ? W_hh[orig * 256 + k] : W_ih[orig * 256 + k];
        __half hi = __float2half_rn(wv);
        __half lo = __float2half_rn(wv - __half2float(hi));
        g_W[m][ug][0][j * 256 + k] = hi;
        g_W[m][ug][1][j * 256 + k] = lo;
    }
    if (idx < 256) {
        g_bias[idx]       = b_ih[idx]       + b_hh[idx];
        g_bias[256 + idx] = b_ih[256 + idx] + b_hh[256 + idx];
        g_bias[512 + idx] = b_ih[512 + idx];
        g_bias[768 + idx] = b_hh[512 + idx];
    }
    if (idx < Tsz * MGN) ((int*)g_flag)[idx] = 0;
}

// ---------------- phase A: xi = x @ W_ih^T (gate-blocked, hi/lo exact) ----------------
__global__ void __launch_bounds__(256, 1) xproj_kernel(const float* __restrict__ x) {
    extern __shared__ __align__(16) char sp[];
    const uint32_t sA = smem_u32(sp);
    const int tid = threadIdx.x, lane = tid & 31, w = tid >> 5;
    const int wm = w & 3, wn = w >> 2;
    const size_t bt0 = (size_t)blockIdx.x * 128;

    // x tile -> fp16 hi/lo A tiles (rows = 128 consecutive (b,t))
    const float4* x4 = (const float4*)(x + bt0 * 256);
    for (int i = tid; i < 8192; i += 256) {
        int row = i >> 6, c4 = i & 63;
        float4 v = __ldg(&x4[(size_t)row * 64 + c4]);
        __half h0 = __float2half_rn(v.x), h1 = __float2half_rn(v.y);
        __half h2 = __float2half_rn(v.z), h3 = __float2half_rn(v.w);
        __half l0 = __float2half_rn(v.x - __half2float(h0));
        __half l1 = __float2half_rn(v.y - __half2float(h1));
        __half l2 = __float2half_rn(v.z - __half2float(h2));
        __half l3 = __float2half_rn(v.w - __half2float(h3));
        uint2 hv = {h2u(__halves2half2(h0, h1)), h2u(__halves2half2(h2, h3))};
        uint2 lv = {h2u(__halves2half2(l0, l1)), h2u(__halves2half2(l2, l3))};
        *(uint2*)(sp + row * AROW + c4 * 8) = hv;
        *(uint2*)(sp + OFF_A2 + row * AROW + c4 * 8) = lv;
    }

#pragma unroll 1
    for (int ug = 0; ug < UGN; ug++) {
        float acc[2][3][2][4];
#pragma unroll
        for (int mt = 0; mt < 2; mt++)
#pragma unroll
            for (int g = 0; g < 3; g++)
#pragma unroll
                for (int j = 0; j < 2; j++)
#pragma unroll
                    for (int e = 0; e < 4; e++) acc[mt][g][j][e] = 0.0f;

#pragma unroll 1
        for (int p = 0; p < 2; p++) {
            __syncthreads();  // A staged / previous gemm reads of W done
            for (int i = tid; i < 3072; i += 256) {
                int j = i >> 5, q = i & 31;
                *(uint4*)(sp + OFF_WX + j * AROW + q * 16) =
                    ((const uint4*)&g_W[0][ug][p][0])[j * 32 + q];
            }
            __syncthreads();
            gemm2(sA, sA + OFF_WX, wm, wn, lane, acc);               // W_p @ x_hi
            if (p == 0)
                gemm2(sA + OFF_A2, sA + OFF_WX, wm, wn, lane, acc);  // W_hi @ x_lo
        }

#pragma unroll
        for (int mt = 0; mt < 2; mt++)
#pragma unroll
            for (int eh = 0; eh < 2; eh++) {
                int rl = 32 * wm + 16 * mt + (lane >> 2) + 8 * eh;
                float* go = g_xi + (bt0 + rl) * 768 + ug * 96 + wn * 16 + 2 * (lane & 3);
#pragma unroll
                for (int g = 0; g < 3; g++)
#pragma unroll
                    for (int j = 0; j < 2; j++) {
                        float2 v = {acc[mt][g][j][eh * 2], acc[mt][g][j][eh * 2 + 1]};
                        *(float2*)(go + g * 32 + j * 8) = v;
                    }
            }
    }
}

// ---------------- recurrence: 128 persistent CTAs, 512 threads (M=64, warp N=24) --------
__global__ void __launch_bounds__(512, 1) gru_rec(const int* __restrict__ seqlen,
                                                  float* __restrict__ out) {
    extern __shared__ __align__(16) char sp[];
    const uint32_t sA = smem_u32(sp);
    const int tid = threadIdx.x, lane = tid & 31, w = tid >> 5;
    const int wm = w & 3, wn = w >> 2;                 // wm: 16-row block, wn: 8-unit block
    const int l16 = lane & 15, h16 = (lane >> 4) & 1;
    const int bg = blockIdx.x >> 3, ug = blockIdx.x & 7;

    // W_hh hi/lo resident all steps
    for (int i = tid; i < 6144; i += 512) {
        int p = i / 3072, r2 = i - p * 3072, j = r2 >> 5, q = r2 & 31;
        *(uint4*)(sp + OFF_W + p * WPASS + j * AROW + q * 16) =
            ((const uint4*)&g_W[1][ug][p][0])[j * 32 + q];
    }
    // A_hi = A_lo = 0 (h0)
    {
        uint4 z = {0, 0, 0, 0};
        for (int i = tid; i < 4224; i += 512) ((uint4*)sp)[i] = z;
    }

    // thread-resident biases (2 units) and seqlen (2 rows)
    const int ucol = 8 * wn + 2 * (lane & 3);          // first of thread's 2 unit-cols
    float br[2], bz[2], bxn[2], bhg[2];
#pragma unroll
    for (int e1 = 0; e1 < 2; e1++) {
        int hu = ug * 32 + ucol + e1;
        br[e1] = g_bias[hu]; bz[e1] = g_bias[256 + hu];
        bxn[e1] = g_bias[512 + hu]; bhg[e1] = g_bias[768 + hu];
    }
    const int row0 = 16 * wm + (lane >> 2);
    int Lr[2];
    Lr[0] = seqlen[bg * 64 + row0];
    Lr[1] = seqlen[bg * 64 + row0 + 8];

    float hold[2][2], hn[2][2];
#pragma unroll
    for (int eh = 0; eh < 2; eh++)
#pragma unroll
        for (int e1 = 0; e1 < 2; e1++) { hold[eh][e1] = 0.0f; hn[eh][e1] = 0.0f; }
    __syncthreads();

    const uint32_t aHiBase = sA + (16 * wm + l16) * AROW + h16 * 16;
    const uint32_t aLoBase = aHiBase + OFF_ALO;
    const uint32_t bRow    = (8 * wn + (lane & 7)) * AROW + ((l16 >> 3) & 1) * 16;

#pragma unroll 1
    for (int t = 0; t < Tsz; t++) {
        // xi preload FIRST — memory latency hides behind the flag wait
        float2 xif[2][3];
#pragma unroll
        for (int eh = 0; eh < 2; eh++) {
            const float* xb = g_xi + ((size_t)(bg * 64 + row0 + 8 * eh) * Tsz + t) * 768 +
                              ug * 96 + ucol;
#pragma unroll
            for (int g = 0; g < 3; g++)
                xif[eh][g] = __ldg((const float2*)(xb + g * 32));
        }

        if (t > 0) {
            // elected-warp spin: one L2 poll stream per CTA instead of 16
            if (w == 0) {
                const int* fp = &g_flag[t - 1][bg];
                int v;
                do { asm volatile("ld.global.acquire.gpu.b32 %0, [%1];" : "=r"(v) : "l"(fp)); }
                while (v < UGN);
            }
            __syncthreads();  // propagate acquire CTA-wide

            // stage h_hi -> A_hi and h_lo -> A_lo via cp.async (g_hx row = 64 uint4)
            const uint4* hr = (const uint4*)(g_hx[(t - 1) & 1] + (size_t)(bg * 64) * 512);
            for (int i = tid; i < 4096; i += 512) {
                int row = i >> 6, rest = i & 63, half = rest >> 5, q = rest & 31;
                cpasync16(sA + half * OFF_ALO + row * AROW + q * 16,
                          hr + (size_t)row * 64 + half * 32 + q);
            }
            asm volatile("cp.async.commit_group;");
            asm volatile("cp.async.wait_group 0;" ::: "memory");
        }
        __syncthreads();

        float acc[3][4];
#pragma unroll
        for (int g = 0; g < 3; g++)
#pragma unroll
            for (int e = 0; e < 4; e++) acc[g][e] = 0.0f;

        // merged 3-pass GEMM: per kc, per gate: {W_hi@h_hi, W_lo@h_hi, W_hi@h_lo}
#pragma unroll 4
        for (int kc = 0; kc < 16; kc++) {
            uint32_t ah[4], al[4];
            ldsm4(ah, aHiBase + kc * 32);
            ldsm4(al, aLoBase + kc * 32);
#pragma unroll
            for (int g = 0; g < 3; g++) {
                uint32_t bh[2], bl[2];
                uint32_t baddr = g * 32 * AROW + bRow + kc * 32;
                ldsm2(bh, sA + OFF_W + baddr);
                ldsm2(bl, sA + OFF_W + WPASS + baddr);
                mma16816(acc[g], ah, bh);
                mma16816(acc[g], ah, bl);
                mma16816(acc[g], al, bh);
            }
        }

        // epilogue: gates + h update; publish straight to g_hx
#pragma unroll
        for (int eh = 0; eh < 2; eh++) {
            float hv2[2];
#pragma unroll
            for (int e1 = 0; e1 < 2; e1++) {
                int e = 2 * eh + e1;
                float xr = e1 ? xif[eh][0].y : xif[eh][0].x;
                float xz = e1 ? xif[eh][1].y : xif[eh][1].x;
                float xn = e1 ? xif[eh][2].y : xif[eh][2].x;
                float rr = sigm(acc[0][e] + xr + br[e1]);
                float zz = sigm(acc[1][e] + xz + bz[e1]);
                float nn = tanh_(xn + bxn[e1] + rr * (acc[2][e] + bhg[e1]));
                float hv = zz * (hold[eh][e1] - nn) + nn;
                hold[eh][e1] = hv;
                if (t + 1 == Lr[eh]) hn[eh][e1] = hv;
                hv2[e1] = hv;
            }
            __half h0 = __float2half_rn(hv2[0]), h1 = __float2half_rn(hv2[1]);
            __half l0 = __float2half_rn(hv2[0] - __half2float(h0));
            __half l1 = __float2half_rn(hv2[1] - __half2float(h1));
            __half* hd = g_hx[t & 1] + (size_t)(bg * 64 + row0 + 8 * eh) * 512 + ug * 32 + ucol;
            *(uint32_t*)hd         = h2u(__halves2half2(h0, h1));
            *(uint32_t*)(hd + 256) = h2u(__halves2half2(l0, l1));
        }
        __threadfence();
        __syncthreads();   // publishes done + all A-tile reads done (safe to restage)
        if (tid == 0) atomicAdd(&g_flag[t][bg], 1);
    }

#pragma unroll
    for (int eh = 0; eh < 2; eh++)
#pragma unroll
        for (int e1 = 0; e1 < 2; e1++)
            out[(size_t)(bg * 64 + row0 + 8 * eh) * 256 + ug * 32 + ucol + e1] = hn[eh][e1];
}

extern "C" void kernel_launch(void* const* d_in, const int* in_sizes, int n_in,
                              void* d_out, int out_size) {
    const float* x      = (const float*)d_in[0];
    const int*   seqlen = (const int*)d_in[1];
    const float* W_ih   = (const float*)d_in[2];
    const float* W_hh   = (const float*)d_in[3];
    const float* b_ih   = (const float*)d_in[4];
    const float* b_hh   = (const float*)d_in[5];
    float*       out    = (float*)d_out;

    static bool init = false;
    if (!init) {
        cudaFuncSetAttribute(xproj_kernel, cudaFuncAttributeMaxDynamicSharedMemorySize, SMEM_XP);
        cudaFuncSetAttribute(gru_rec, cudaFuncAttributeMaxDynamicSharedMemorySize, SMEM_REC);
        init = true;
    }
    prep_kernel<<<1536, 256>>>(W_ih, W_hh, b_ih, b_hh);
    xproj_kernel<<<(Bsz * Tsz) / 128, 256, SMEM_XP>>>(x);
    gru_rec<<<MGN * UGN, 512, SMEM_REC>>>(seqlen, out);
}

// round 14
// speedup vs baseline: 7.0732x; 1.2606x over previous
#include <cuda_runtime.h>
#include <cuda_fp16.h>
#include <cstdint>

// B=1024, T=512, I=H=256, 3H=768
#define Bsz 1024
#define Tsz 512
#define MGN 16     // batch groups (64 rows each)
#define UGN 8      // unit groups (32 units -> 96 gate rows, gate-blocked r|z|n)

// ---------------- device scratch (static) ----------------
__device__ float g_xi[(size_t)Bsz * Tsz * 768];              // xi (no bias), col = ug*96+gate*32+u
__device__ __align__(16) __half g_W[2][UGN][2][96 * 256];    // [mat][ug][hi/lo][j*256+k]
// h exchange (fp16), double buffered: row = 256 halves (one per unit)
__device__ __align__(16) __half g_hx[2][(size_t)Bsz * 256];
__device__ int   g_flag[Tsz][MGN];
__device__ float g_bias[1024];  // [0]=br(ih+hh) [256]=bz(ih+hh) [512]=b_ih_n [768]=b_hh_n

// ---------------- SMEM layouts (bytes) ----------------
#define AROW  528                 // 264 halves per row (pad keeps ldsm phases conflict-free)
// gru_rec: A(64x528=33792) | W 2 passes (101376)
#define OFF_W   33792
#define WPASS   50688
#define SMEM_REC (OFF_W + 2 * WPASS)
// xproj: A(128x528=67584) | W 1 pass (50688)
#define OFF_WX  67584
#define SMEM_XP (OFF_WX + WPASS)

// ---------------- helpers ----------------
__device__ __forceinline__ uint32_t smem_u32(const void* p) {
    uint32_t a;
    asm("{ .reg .u64 t; cvta.to.shared.u64 t, %1; cvt.u32.u64 %0, t; }" : "=r"(a) : "l"(p));
    return a;
}
__device__ __forceinline__ void ldsm4(uint32_t* r, uint32_t a) {
    asm volatile("ldmatrix.sync.aligned.m8n8.x4.shared.b16 {%0,%1,%2,%3}, [%4];"
                 : "=r"(r[0]), "=r"(r[1]), "=r"(r[2]), "=r"(r[3]) : "r"(a));
}
__device__ __forceinline__ void ldsm2(uint32_t* r, uint32_t a) {
    asm volatile("ldmatrix.sync.aligned.m8n8.x2.shared.b16 {%0,%1}, [%2];"
                 : "=r"(r[0]), "=r"(r[1]) : "r"(a));
}
__device__ __forceinline__ void mma16816(float* d, const uint32_t* a, const uint32_t* b) {
    asm volatile("mma.sync.aligned.m16n8k16.row.col.f32.f16.f16.f32 "
                 "{%0,%1,%2,%3}, {%4,%5,%6,%7}, {%8,%9}, {%0,%1,%2,%3};"
                 : "+f"(d[0]), "+f"(d[1]), "+f"(d[2]), "+f"(d[3])
                 : "r"(a[0]), "r"(a[1]), "r"(a[2]), "r"(a[3]), "r"(b[0]), "r"(b[1]));
}
__device__ __forceinline__ void cpasync16(uint32_t dst, const void* src) {
    asm volatile("cp.async.ca.shared.global [%0], [%1], 16;" :: "r"(dst), "l"(src));
}
__device__ __forceinline__ float sigm(float a)  {
    return __fdividef(1.0f, 1.0f + __expf(-a));
}
__device__ __forceinline__ float tanh_(float a) {
    return 1.0f - __fdividef(2.0f, 1.0f + __expf(2.0f * a));
}
__device__ __forceinline__ uint32_t h2u(__half2 h) { return *reinterpret_cast<uint32_t*>(&h); }

// K=256 pass, M=32 rows per warp (mt=2 tiles of 16) — used by xproj (M=128, warps 4wm x 2wn)
__device__ __forceinline__ void gemm2(uint32_t sAb, uint32_t sWb, int wm, int wn, int lane,
                                      float acc[2][3][2][4]) {
    const int l16 = lane & 15, h16 = (lane >> 4) & 1;
    const uint32_t aBase = sAb + (32 * wm + l16) * AROW + h16 * 16;
    const uint32_t bBase = sWb + (wn * 16 + l16) * AROW + h16 * 16;
#pragma unroll 4
    for (int kc = 0; kc < 16; kc++) {
        uint32_t a[2][4];
        ldsm4(a[0], aBase + kc * 32);
        ldsm4(a[1], aBase + 16 * AROW + kc * 32);
#pragma unroll
        for (int g = 0; g < 3; g++) {
            uint32_t b[4];
            ldsm4(b, bBase + g * 32 * AROW + kc * 32);
            uint32_t bj0[2] = {b[0], b[2]}, bj1[2] = {b[1], b[3]};
#pragma unroll
            for (int mt = 0; mt < 2; mt++) {
                mma16816(acc[mt][g][0], a[mt], bj0);
                mma16816(acc[mt][g][1], a[mt], bj1);
            }
        }
    }
}

// ---------------- prep ----------------
__global__ void prep_kernel(const float* __restrict__ W_ih, const float* __restrict__ W_hh,
                            const float* __restrict__ b_ih, const float* __restrict__ b_hh) {
    int idx = blockIdx.x * 256 + threadIdx.x;
    if (idx < 2 * UGN * 96 * 256) {
        int k = idx & 255, rest = idx >> 8;
        int j = rest % 96, ug = (rest / 96) & 7, m = rest / 768;
        int gate = j >> 5, u = j & 31;
        int orig = gate * 256 + ug * 32 + u;
        float wv = m ? W_hh[orig * 256 + k] : W_ih[orig * 256 + k];
        __half hi = __float2half_rn(wv);
        __half lo = __float2half_rn(wv - __half2float(hi));
        g_W[m][ug][0][j * 256 + k] = hi;
        g_W[m][ug][1][j * 256 + k] = lo;
    }
    if (idx < 256) {
        g_bias[idx]       = b_ih[idx]       + b_hh[idx];
        g_bias[256 + idx] = b_ih[256 + idx] + b_hh[256 + idx];
        g_bias[512 + idx] = b_ih[512 + idx];
        g_bias[768 + idx] = b_hh[512 + idx];
    }
    if (idx < Tsz * MGN) ((int*)g_flag)[idx] = 0;
}

// ---------------- phase A: xi = x @ (W_hi + W_lo)^T, x in fp16 ----------------
__global__ void __launch_bounds__(256, 1) xproj_kernel(const float* __restrict__ x) {
    extern __shared__ __align__(16) char sp[];
    const uint32_t sA = smem_u32(sp);
    const int tid = threadIdx.x, lane = tid & 31, w = tid >> 5;
    const int wm = w & 3, wn = w >> 2;
    const size_t bt0 = (size_t)blockIdx.x * 128;

    // x tile -> fp16 A (rows = 128 consecutive (b,t))
    const float4* x4 = (const float4*)(x + bt0 * 256);
    for (int i = tid; i < 8192; i += 256) {
        int row = i >> 6, c4 = i & 63;
        float4 v = __ldg(&x4[(size_t)row * 64 + c4]);
        uint2 hv = {h2u(__floats2half2_rn(v.x, v.y)), h2u(__floats2half2_rn(v.z, v.w))};
        *(uint2*)(sp + row * AROW + c4 * 8) = hv;
    }

#pragma unroll 1
    for (int ug = 0; ug < UGN; ug++) {
        float acc[2][3][2][4];
#pragma unroll
        for (int mt = 0; mt < 2; mt++)
#pragma unroll
            for (int g = 0; g < 3; g++)
#pragma unroll
                for (int j = 0; j < 2; j++)
#pragma unroll
                    for (int e = 0; e < 4; e++) acc[mt][g][j][e] = 0.0f;

#pragma unroll 1
        for (int p = 0; p < 2; p++) {
            __syncthreads();  // A staged / previous gemm reads of W done
            for (int i = tid; i < 3072; i += 256) {
                int j = i >> 5, q = i & 31;
                *(uint4*)(sp + OFF_WX + j * AROW + q * 16) =
                    ((const uint4*)&g_W[0][ug][p][0])[j * 32 + q];
            }
            __syncthreads();
            gemm2(sA, sA + OFF_WX, wm, wn, lane, acc);   // W_p @ x
        }

#pragma unroll
        for (int mt = 0; mt < 2; mt++)
#pragma unroll
            for (int eh = 0; eh < 2; eh++) {
                int rl = 32 * wm + 16 * mt + (lane >> 2) + 8 * eh;
                float* go = g_xi + (bt0 + rl) * 768 + ug * 96 + wn * 16 + 2 * (lane & 3);
#pragma unroll
                for (int g = 0; g < 3; g++)
#pragma unroll
                    for (int j = 0; j < 2; j++) {
                        float2 v = {acc[mt][g][j][eh * 2], acc[mt][g][j][eh * 2 + 1]};
                        *(float2*)(go + g * 32 + j * 8) = v;
                    }
            }
    }
}

// ---------------- recurrence: 128 persistent CTAs, 512 threads (M=64, warp N=24) --------
__global__ void __launch_bounds__(512, 1) gru_rec(const int* __restrict__ seqlen,
                                                  float* __restrict__ out) {
    extern __shared__ __align__(16) char sp[];
    const uint32_t sA = smem_u32(sp);
    const int tid = threadIdx.x, lane = tid & 31, w = tid >> 5;
    const int wm = w & 3, wn = w >> 2;                 // wm: 16-row block, wn: 8-unit block
    const int l16 = lane & 15, h16 = (lane >> 4) & 1;
    const int bg = blockIdx.x >> 3, ug = blockIdx.x & 7;

    // W_hh hi/lo resident all steps
    for (int i = tid; i < 6144; i += 512) {
        int p = i / 3072, r2 = i - p * 3072, j = r2 >> 5, q = r2 & 31;
        *(uint4*)(sp + OFF_W + p * WPASS + j * AROW + q * 16) =
            ((const uint4*)&g_W[1][ug][p][0])[j * 32 + q];
    }
    // A = 0 (h0)
    {
        uint4 z = {0, 0, 0, 0};
        for (int i = tid; i < 2112; i += 512) ((uint4*)sp)[i] = z;
    }

    // thread-resident biases (2 units) and seqlen (2 rows)
    const int ucol = 8 * wn + 2 * (lane & 3);          // first of thread's 2 unit-cols
    float br[2], bz[2], bxn[2], bhg[2];
#pragma unroll
    for (int e1 = 0; e1 < 2; e1++) {
        int hu = ug * 32 + ucol + e1;
        br[e1] = g_bias[hu]; bz[e1] = g_bias[256 + hu];
        bxn[e1] = g_bias[512 + hu]; bhg[e1] = g_bias[768 + hu];
    }
    const int row0 = 16 * wm + (lane >> 2);
    int Lr[2];
    Lr[0] = seqlen[bg * 64 + row0];
    Lr[1] = seqlen[bg * 64 + row0 + 8];

    float hold[2][2], hn[2][2];
#pragma unroll
    for (int eh = 0; eh < 2; eh++)
#pragma unroll
        for (int e1 = 0; e1 < 2; e1++) { hold[eh][e1] = 0.0f; hn[eh][e1] = 0.0f; }
    __syncthreads();

    const uint32_t aBase = sA + (16 * wm + l16) * AROW + h16 * 16;
    const uint32_t bRow  = (8 * wn + (lane & 7)) * AROW + ((l16 >> 3) & 1) * 16;

#pragma unroll 1
    for (int t = 0; t < Tsz; t++) {
        // xi preload FIRST — memory latency hides behind the flag wait
        float2 xif[2][3];
#pragma unroll
        for (int eh = 0; eh < 2; eh++) {
            const float* xb = g_xi + ((size_t)(bg * 64 + row0 + 8 * eh) * Tsz + t) * 768 +
                              ug * 96 + ucol;
#pragma unroll
            for (int g = 0; g < 3; g++)
                xif[eh][g] = __ldg((const float2*)(xb + g * 32));
        }

        if (t > 0) {
            // elected-warp spin: one L2 poll stream per CTA
            if (w == 0) {
                const int* fp = &g_flag[t - 1][bg];
                int v;
                do { asm volatile("ld.global.acquire.gpu.b32 %0, [%1];" : "=r"(v) : "l"(fp)); }
                while (v < UGN);
            }
            __syncthreads();  // propagate acquire CTA-wide

            // stage h (fp16) -> A via cp.async (g_hx row = 32 uint4)
            const uint4* hr = (const uint4*)(g_hx[(t - 1) & 1] + (size_t)(bg * 64) * 256);
            for (int i = tid; i < 2048; i += 512) {
                int row = i >> 5, q = i & 31;
                cpasync16(sA + row * AROW + q * 16, hr + (size_t)row * 32 + q);
            }
            asm volatile("cp.async.commit_group;");
            asm volatile("cp.async.wait_group 0;" ::: "memory");
        }
        __syncthreads();

        float acc[3][4];
#pragma unroll
        for (int g = 0; g < 3; g++)
#pragma unroll
            for (int e = 0; e < 4; e++) acc[g][e] = 0.0f;

        // 2-pass GEMM merged: per kc, per gate: {W_hi@h, W_lo@h}
#pragma unroll 4
        for (int kc = 0; kc < 16; kc++) {
            uint32_t ah[4];
            ldsm4(ah, aBase + kc * 32);
#pragma unroll
            for (int g = 0; g < 3; g++) {
                uint32_t bh[2], bl[2];
                uint32_t baddr = g * 32 * AROW + bRow + kc * 32;
                ldsm2(bh, sA + OFF_W + baddr);
                ldsm2(bl, sA + OFF_W + WPASS + baddr);
                mma16816(acc[g], ah, bh);
                mma16816(acc[g], ah, bl);
            }
        }

        // epilogue: gates + h update (hold stays fp32); publish fp16 h to g_hx
#pragma unroll
        for (int eh = 0; eh < 2; eh++) {
            float hv2[2];
#pragma unroll
            for (int e1 = 0; e1 < 2; e1++) {
                int e = 2 * eh + e1;
                float xr = e1 ? xif[eh][0].y : xif[eh][0].x;
                float xz = e1 ? xif[eh][1].y : xif[eh][1].x;
                float xn = e1 ? xif[eh][2].y : xif[eh][2].x;
                float rr = sigm(acc[0][e] + xr + br[e1]);
                float zz = sigm(acc[1][e] + xz + bz[e1]);
                float nn = tanh_(xn + bxn[e1] + rr * (acc[2][e] + bhg[e1]));
                float hv = zz * (hold[eh][e1] - nn) + nn;
                hold[eh][e1] = hv;
                if (t + 1 == Lr[eh]) hn[eh][e1] = hv;
                hv2[e1] = hv;
            }
            __half* hd = g_hx[t & 1] + (size_t)(bg * 64 + row0 + 8 * eh) * 256 + ug * 32 + ucol;
            *(uint32_t*)hd = h2u(__floats2half2_rn(hv2[0], hv2[1]));
        }
        __syncthreads();   // publishes done + all A-tile reads done (safe to restage)
        if (tid == 0) {
            __threadfence();            // tid0 observed all CTA stores via the bar; gpu-scope release
            atomicAdd(&g_flag[t][bg], 1);
        }
    }

#pragma unroll
    for (int eh = 0; eh < 2; eh++)
#pragma unroll
        for (int e1 = 0; e1 < 2; e1++)
            out[(size_t)(bg * 64 + row0 + 8 * eh) * 256 + ug * 32 + ucol + e1] = hn[eh][e1];
}

extern "C" void kernel_launch(void* const* d_in, const int* in_sizes, int n_in,
                              void* d_out, int out_size) {
    const float* x      = (const float*)d_in[0];
    const int*   seqlen = (const int*)d_in[1];
    const float* W_ih   = (const float*)d_in[2];
    const float* W_hh   = (const float*)d_in[3];
    const float* b_ih   = (const float*)d_in[4];
    const float* b_hh   = (const float*)d_in[5];
    float*       out    = (float*)d_out;

    static bool init = false;
    if (!init) {
        cudaFuncSetAttribute(xproj_kernel, cudaFuncAttributeMaxDynamicSharedMemorySize, SMEM_XP);
        cudaFuncSetAttribute(gru_rec, cudaFuncAttributeMaxDynamicSharedMemorySize, SMEM_REC);
        init = true;
    }
    prep_kernel<<<1536, 256>>>(W_ih, W_hh, b_ih, b_hh);
    xproj_kernel<<<(Bsz * Tsz) / 128, 256, SMEM_XP>>>(x);
    gru_rec<<<MGN * UGN, 512, SMEM_REC>>>(seqlen, out);
}

// round 15
// speedup vs baseline: 7.9115x; 1.1185x over previous
#include <cuda_runtime.h>
#include <cuda_fp16.h>
#include <cstdint>

// B=1024, T=512, I=H=256, 3H=768
#define Bsz 1024
#define Tsz 512
#define MGN 16     // batch groups (64 rows each)
#define UGN 8      // unit groups (32 units -> 96 gate rows, gate-blocked r|z|n)

// ---------------- device scratch (static) ----------------
__device__ float g_xi[(size_t)Bsz * Tsz * 768];              // xi (no bias), col = ug*96+gate*32+u
__device__ __align__(16) __half g_W[2][UGN][2][96 * 256];    // [mat][ug][hi/lo][j*256+k]
// h exchange (fp16), double buffered: row = 256 halves (one per unit)
__device__ __align__(16) __half g_hx[2][(size_t)Bsz * 256];
__device__ int   g_flag[Tsz][MGN];
__device__ float g_bias[1024];  // [0]=br(ih+hh) [256]=bz(ih+hh) [512]=b_ih_n [768]=b_hh_n

// ---------------- SMEM layouts (bytes) ----------------
#define AROW  528                 // 264 halves per row (pad keeps ldsm phases conflict-free)
// gru_rec: A(64x528=33792) | W_hi (50688)
#define OFF_W   33792
#define WPASS   50688
#define SMEM_REC (OFF_W + WPASS)
// xproj: A(128x528=67584) | W 1 pass (50688)
#define OFF_WX  67584
#define SMEM_XP (OFF_WX + WPASS)

// ---------------- helpers ----------------
__device__ __forceinline__ uint32_t smem_u32(const void* p) {
    uint32_t a;
    asm("{ .reg .u64 t; cvta.to.shared.u64 t, %1; cvt.u32.u64 %0, t; }" : "=r"(a) : "l"(p));
    return a;
}
__device__ __forceinline__ void ldsm4(uint32_t* r, uint32_t a) {
    asm volatile("ldmatrix.sync.aligned.m8n8.x4.shared.b16 {%0,%1,%2,%3}, [%4];"
                 : "=r"(r[0]), "=r"(r[1]), "=r"(r[2]), "=r"(r[3]) : "r"(a));
}
__device__ __forceinline__ void ldsm2(uint32_t* r, uint32_t a) {
    asm volatile("ldmatrix.sync.aligned.m8n8.x2.shared.b16 {%0,%1}, [%2];"
                 : "=r"(r[0]), "=r"(r[1]) : "r"(a));
}
__device__ __forceinline__ void mma16816(float* d, const uint32_t* a, const uint32_t* b) {
    asm volatile("mma.sync.aligned.m16n8k16.row.col.f32.f16.f16.f32 "
                 "{%0,%1,%2,%3}, {%4,%5,%6,%7}, {%8,%9}, {%0,%1,%2,%3};"
                 : "+f"(d[0]), "+f"(d[1]), "+f"(d[2]), "+f"(d[3])
                 : "r"(a[0]), "r"(a[1]), "r"(a[2]), "r"(a[3]), "r"(b[0]), "r"(b[1]));
}
__device__ __forceinline__ void cpasync16(uint32_t dst, const void* src) {
    asm volatile("cp.async.ca.shared.global [%0], [%1], 16;" :: "r"(dst), "l"(src));
}
__device__ __forceinline__ float sigm(float a)  {
    return __fdividef(1.0f, 1.0f + __expf(-a));
}
__device__ __forceinline__ float tanh_(float a) {
    return 1.0f - __fdividef(2.0f, 1.0f + __expf(2.0f * a));
}
__device__ __forceinline__ uint32_t h2u(__half2 h) { return *reinterpret_cast<uint32_t*>(&h); }

// K=256 pass, M=32 rows per warp (mt=2 tiles of 16) — used by xproj (M=128, warps 4wm x 2wn)
__device__ __forceinline__ void gemm2(uint32_t sAb, uint32_t sWb, int wm, int wn, int lane,
                                      float acc[2][3][2][4]) {
    const int l16 = lane & 15, h16 = (lane >> 4) & 1;
    const uint32_t aBase = sAb + (32 * wm + l16) * AROW + h16 * 16;
    const uint32_t bBase = sWb + (wn * 16 + l16) * AROW + h16 * 16;
#pragma unroll 4
    for (int kc = 0; kc < 16; kc++) {
        uint32_t a[2][4];
        ldsm4(a[0], aBase + kc * 32);
        ldsm4(a[1], aBase + 16 * AROW + kc * 32);
#pragma unroll
        for (int g = 0; g < 3; g++) {
            uint32_t b[4];
            ldsm4(b, bBase + g * 32 * AROW + kc * 32);
            uint32_t bj0[2] = {b[0], b[2]}, bj1[2] = {b[1], b[3]};
#pragma unroll
            for (int mt = 0; mt < 2; mt++) {
                mma16816(acc[mt][g][0], a[mt], bj0);
                mma16816(acc[mt][g][1], a[mt], bj1);
            }
        }
    }
}

// ---------------- prep ----------------
__global__ void prep_kernel(const float* __restrict__ W_ih, const float* __restrict__ W_hh,
                            const float* __restrict__ b_ih, const float* __restrict__ b_hh) {
    int idx = blockIdx.x * 256 + threadIdx.x;
    if (idx < 2 * UGN * 96 * 256) {
        int k = idx & 255, rest = idx >> 8;
        int j = rest % 96, ug = (rest / 96) & 7, m = rest / 768;
        int gate = j >> 5, u = j & 31;
        int orig = gate * 256 + ug * 32 + u;
        float wv = m ? W_hh[orig * 256 + k] : W_ih[orig * 256 + k];
        __half hi = __float2half_rn(wv);
        __half lo = __float2half_rn(wv - __half2float(hi));
        g_W[m][ug][0][j * 256 + k] = hi;
        g_W[m][ug][1][j * 256 + k] = lo;
    }
    if (idx < 256) {
        g_bias[idx]       = b_ih[idx]       + b_hh[idx];
        g_bias[256 + idx] = b_ih[256 + idx] + b_hh[256 + idx];
        g_bias[512 + idx] = b_ih[512 + idx];
        g_bias[768 + idx] = b_hh[512 + idx];
    }
    if (idx < Tsz * MGN) ((int*)g_flag)[idx] = 0;
}

// ---------------- phase A: xi = x @ (W_hi + W_lo)^T, x in fp16 ----------------
__global__ void __launch_bounds__(256, 1) xproj_kernel(const float* __restrict__ x) {
    extern __shared__ __align__(16) char sp[];
    const uint32_t sA = smem_u32(sp);
    const int tid = threadIdx.x, lane = tid & 31, w = tid >> 5;
    const int wm = w & 3, wn = w >> 2;
    const size_t bt0 = (size_t)blockIdx.x * 128;

    // x tile -> fp16 A (rows = 128 consecutive (b,t))
    const float4* x4 = (const float4*)(x + bt0 * 256);
    for (int i = tid; i < 8192; i += 256) {
        int row = i >> 6, c4 = i & 63;
        float4 v = __ldg(&x4[(size_t)row * 64 + c4]);
        uint2 hv = {h2u(__floats2half2_rn(v.x, v.y)), h2u(__floats2half2_rn(v.z, v.w))};
        *(uint2*)(sp + row * AROW + c4 * 8) = hv;
    }

#pragma unroll 1
    for (int ug = 0; ug < UGN; ug++) {
        float acc[2][3][2][4];
#pragma unroll
        for (int mt = 0; mt < 2; mt++)
#pragma unroll
            for (int g = 0; g < 3; g++)
#pragma unroll
                for (int j = 0; j < 2; j++)
#pragma unroll
                    for (int e = 0; e < 4; e++) acc[mt][g][j][e] = 0.0f;

#pragma unroll 1
        for (int p = 0; p < 2; p++) {
            __syncthreads();  // A staged / previous gemm reads of W done
            for (int i = tid; i < 3072; i += 256) {
                int j = i >> 5, q = i & 31;
                *(uint4*)(sp + OFF_WX + j * AROW + q * 16) =
                    ((const uint4*)&g_W[0][ug][p][0])[j * 32 + q];
            }
            __syncthreads();
            gemm2(sA, sA + OFF_WX, wm, wn, lane, acc);   // W_p @ x
        }

#pragma unroll
        for (int mt = 0; mt < 2; mt++)
#pragma unroll
            for (int eh = 0; eh < 2; eh++) {
                int rl = 32 * wm + 16 * mt + (lane >> 2) + 8 * eh;
                float* go = g_xi + (bt0 + rl) * 768 + ug * 96 + wn * 16 + 2 * (lane & 3);
#pragma unroll
                for (int g = 0; g < 3; g++)
#pragma unroll
                    for (int j = 0; j < 2; j++) {
                        float2 v = {acc[mt][g][j][eh * 2], acc[mt][g][j][eh * 2 + 1]};
                        *(float2*)(go + g * 32 + j * 8) = v;
                    }
            }
    }
}

// ---------------- recurrence: 128 persistent CTAs, 512 threads (M=64, warp N=24) --------
// Single-pass W_hh (hi only): the dropped lo-term injects ~1.2e-4/step preact noise,
// same order as the h-fp16 exchange noise already accepted; halves B-side SMEM traffic.
__global__ void __launch_bounds__(512, 1) gru_rec(const int* __restrict__ seqlen,
                                                  float* __restrict__ out) {
    extern __shared__ __align__(16) char sp[];
    const uint32_t sA = smem_u32(sp);
    const int tid = threadIdx.x, lane = tid & 31, w = tid >> 5;
    const int wm = w & 3, wn = w >> 2;                 // wm: 16-row block, wn: 8-unit block
    const int l16 = lane & 15, h16 = (lane >> 4) & 1;
    const int bg = blockIdx.x >> 3, ug = blockIdx.x & 7;

    // W_hh hi resident all steps
    for (int i = tid; i < 3072; i += 512) {
        int j = i >> 5, q = i & 31;
        *(uint4*)(sp + OFF_W + j * AROW + q * 16) =
            ((const uint4*)&g_W[1][ug][0][0])[j * 32 + q];
    }
    // A = 0 (h0)
    {
        uint4 z = {0, 0, 0, 0};
        for (int i = tid; i < 2112; i += 512) ((uint4*)sp)[i] = z;
    }

    // thread-resident biases (2 units) and seqlen (2 rows)
    const int ucol = 8 * wn + 2 * (lane & 3);          // first of thread's 2 unit-cols
    float br[2], bz[2], bxn[2], bhg[2];
#pragma unroll
    for (int e1 = 0; e1 < 2; e1++) {
        int hu = ug * 32 + ucol + e1;
        br[e1] = g_bias[hu]; bz[e1] = g_bias[256 + hu];
        bxn[e1] = g_bias[512 + hu]; bhg[e1] = g_bias[768 + hu];
    }
    const int row0 = 16 * wm + (lane >> 2);
    int Lr[2];
    Lr[0] = seqlen[bg * 64 + row0];
    Lr[1] = seqlen[bg * 64 + row0 + 8];

    float hold[2][2], hn[2][2];
#pragma unroll
    for (int eh = 0; eh < 2; eh++)
#pragma unroll
        for (int e1 = 0; e1 < 2; e1++) { hold[eh][e1] = 0.0f; hn[eh][e1] = 0.0f; }
    __syncthreads();

    const uint32_t aBase = sA + (16 * wm + l16) * AROW + h16 * 16;
    const uint32_t bRow  = (8 * wn + (lane & 7)) * AROW + ((l16 >> 3) & 1) * 16;

#pragma unroll 1
    for (int t = 0; t < Tsz; t++) {
        // xi preload FIRST — memory latency hides behind the flag wait
        float2 xif[2][3];
#pragma unroll
        for (int eh = 0; eh < 2; eh++) {
            const float* xb = g_xi + ((size_t)(bg * 64 + row0 + 8 * eh) * Tsz + t) * 768 +
                              ug * 96 + ucol;
#pragma unroll
            for (int g = 0; g < 3; g++)
                xif[eh][g] = __ldg((const float2*)(xb + g * 32));
        }

        if (t > 0) {
            // elected-warp spin: one L2 poll stream per CTA
            if (w == 0) {
                const int* fp = &g_flag[t - 1][bg];
                int v;
                do { asm volatile("ld.global.acquire.gpu.b32 %0, [%1];" : "=r"(v) : "l"(fp)); }
                while (v < UGN);
            }
            __syncthreads();  // propagate acquire CTA-wide

            // stage h (fp16) -> A via cp.async (g_hx row = 32 uint4)
            const uint4* hr = (const uint4*)(g_hx[(t - 1) & 1] + (size_t)(bg * 64) * 256);
            for (int i = tid; i < 2048; i += 512) {
                int row = i >> 5, q = i & 31;
                cpasync16(sA + row * AROW + q * 16, hr + (size_t)row * 32 + q);
            }
            asm volatile("cp.async.commit_group;");
            asm volatile("cp.async.wait_group 0;" ::: "memory");
        }
        __syncthreads();

        float acc[3][4];
#pragma unroll
        for (int g = 0; g < 3; g++)
#pragma unroll
            for (int e = 0; e < 4; e++) acc[g][e] = 0.0f;

        // single-pass GEMM: per kc, per gate: W_hi @ h
#pragma unroll 4
        for (int kc = 0; kc < 16; kc++) {
            uint32_t ah[4];
            ldsm4(ah, aBase + kc * 32);
#pragma unroll
            for (int g = 0; g < 3; g++) {
                uint32_t bh[2];
                ldsm2(bh, sA + OFF_W + g * 32 * AROW + bRow + kc * 32);
                mma16816(acc[g], ah, bh);
            }
        }

        // epilogue: gates + h update (hold stays fp32); publish fp16 h to g_hx
#pragma unroll
        for (int eh = 0; eh < 2; eh++) {
            float hv2[2];
#pragma unroll
            for (int e1 = 0; e1 < 2; e1++) {
                int e = 2 * eh + e1;
                float xr = e1 ? xif[eh][0].y : xif[eh][0].x;
                float xz = e1 ? xif[eh][1].y : xif[eh][1].x;
                float xn = e1 ? xif[eh][2].y : xif[eh][2].x;
                float rr = sigm(acc[0][e] + xr + br[e1]);
                float zz = sigm(acc[1][e] + xz + bz[e1]);
                float nn = tanh_(xn + bxn[e1] + rr * (acc[2][e] + bhg[e1]));
                float hv = zz * (hold[eh][e1] - nn) + nn;
                hold[eh][e1] = hv;
                if (t + 1 == Lr[eh]) hn[eh][e1] = hv;
                hv2[e1] = hv;
            }
            __half* hd = g_hx[t & 1] + (size_t)(bg * 64 + row0 + 8 * eh) * 256 + ug * 32 + ucol;
            *(uint32_t*)hd = h2u(__floats2half2_rn(hv2[0], hv2[1]));
        }
        __syncthreads();   // publishes done + all A-tile reads done (safe to restage)
        if (tid == 0) {
            __threadfence();            // release: bar made CTA stores visible to tid0's fence
            atomicAdd(&g_flag[t][bg], 1);
        }
    }

#pragma unroll
    for (int eh = 0; eh < 2; eh++)
#pragma unroll
        for (int e1 = 0; e1 < 2; e1++)
            out[(size_t)(bg * 64 + row0 + 8 * eh) * 256 + ug * 32 + ucol + e1] = hn[eh][e1];
}

extern "C" void kernel_launch(void* const* d_in, const int* in_sizes, int n_in,
                              void* d_out, int out_size) {
    const float* x      = (const float*)d_in[0];
    const int*   seqlen = (const int*)d_in[1];
    const float* W_ih   = (const float*)d_in[2];
    const float* W_hh   = (const float*)d_in[3];
    const float* b_ih   = (const float*)d_in[4];
    const float* b_hh   = (const float*)d_in[5];
    float*       out    = (float*)d_out;

    static bool init = false;
    if (!init) {
        cudaFuncSetAttribute(xproj_kernel, cudaFuncAttributeMaxDynamicSharedMemorySize, SMEM_XP);
        cudaFuncSetAttribute(gru_rec, cudaFuncAttributeMaxDynamicSharedMemorySize, SMEM_REC);
        init = true;
    }
    prep_kernel<<<1536, 256>>>(W_ih, W_hh, b_ih, b_hh);
    xproj_kernel<<<(Bsz * Tsz) / 128, 256, SMEM_XP>>>(x);
    gru_rec<<<MGN * UGN, 512, SMEM_REC>>>(seqlen, out);
}

// round 16
// speedup vs baseline: 9.7876x; 1.2371x over previous
#include <cuda_runtime.h>
#include <cuda_fp16.h>
#include <cstdint>

// B=1024, T=512, I=H=256, 3H=768
#define Bsz 1024
#define Tsz 512
#define MGN 16     // batch groups (64 rows each)
#define UGN 8      // unit groups (32 units -> 96 gate rows, gate-blocked r|z|n)

// ---------------- device scratch (static) ----------------
// xi (no bias), T-MAJOR: index = (t*Bsz + b)*768 + col, col = ug*96+gate*32+u.
// At step t a CTA reads a contiguous 64-row block -> full 32B sectors (was 4x amplified).
__device__ float g_xi[(size_t)Bsz * Tsz * 768];
__device__ __align__(16) __half g_W[2][UGN][2][96 * 256];    // [mat][ug][hi/lo][j*256+k]
// h exchange (fp16), double buffered: row = 256 halves (one per unit)
__device__ __align__(16) __half g_hx[2][(size_t)Bsz * 256];
__device__ int   g_flag[Tsz][MGN];
__device__ float g_bias[1024];  // [0]=br(ih+hh) [256]=bz(ih+hh) [512]=b_ih_n [768]=b_hh_n

// ---------------- SMEM layouts (bytes) ----------------
#define AROW  528                 // 264 halves per row (pad keeps ldsm phases conflict-free)
// gru_rec: A(64x528=33792) | W_hi (50688)
#define OFF_W   33792
#define WPASS   50688
#define SMEM_REC (OFF_W + WPASS)
// xproj: A(128x528=67584) | W_hi (50688)
#define OFF_WX  67584
#define SMEM_XP (OFF_WX + WPASS)

// ---------------- helpers ----------------
__device__ __forceinline__ uint32_t smem_u32(const void* p) {
    uint32_t a;
    asm("{ .reg .u64 t; cvta.to.shared.u64 t, %1; cvt.u32.u64 %0, t; }" : "=r"(a) : "l"(p));
    return a;
}
__device__ __forceinline__ void ldsm4(uint32_t* r, uint32_t a) {
    asm volatile("ldmatrix.sync.aligned.m8n8.x4.shared.b16 {%0,%1,%2,%3}, [%4];"
                 : "=r"(r[0]), "=r"(r[1]), "=r"(r[2]), "=r"(r[3]) : "r"(a));
}
__device__ __forceinline__ void ldsm2(uint32_t* r, uint32_t a) {
    asm volatile("ldmatrix.sync.aligned.m8n8.x2.shared.b16 {%0,%1}, [%2];"
                 : "=r"(r[0]), "=r"(r[1]) : "r"(a));
}
__device__ __forceinline__ void mma16816(float* d, const uint32_t* a, const uint32_t* b) {
    asm volatile("mma.sync.aligned.m16n8k16.row.col.f32.f16.f16.f32 "
                 "{%0,%1,%2,%3}, {%4,%5,%6,%7}, {%8,%9}, {%0,%1,%2,%3};"
                 : "+f"(d[0]), "+f"(d[1]), "+f"(d[2]), "+f"(d[3])
                 : "r"(a[0]), "r"(a[1]), "r"(a[2]), "r"(a[3]), "r"(b[0]), "r"(b[1]));
}
__device__ __forceinline__ void cpasync16(uint32_t dst, const void* src) {
    asm volatile("cp.async.ca.shared.global [%0], [%1], 16;" :: "r"(dst), "l"(src));
}
__device__ __forceinline__ float sigm(float a)  {
    return __fdividef(1.0f, 1.0f + __expf(-a));
}
__device__ __forceinline__ float tanh_(float a) {
    return 1.0f - __fdividef(2.0f, 1.0f + __expf(2.0f * a));
}
__device__ __forceinline__ uint32_t h2u(__half2 h) { return *reinterpret_cast<uint32_t*>(&h); }

// K=256 pass, M=32 rows per warp (mt=2 tiles of 16) — used by xproj (M=128, warps 4wm x 2wn)
__device__ __forceinline__ void gemm2(uint32_t sAb, uint32_t sWb, int wm, int wn, int lane,
                                      float acc[2][3][2][4]) {
    const int l16 = lane & 15, h16 = (lane >> 4) & 1;
    const uint32_t aBase = sAb + (32 * wm + l16) * AROW + h16 * 16;
    const uint32_t bBase = sWb + (wn * 16 + l16) * AROW + h16 * 16;
#pragma unroll 4
    for (int kc = 0; kc < 16; kc++) {
        uint32_t a[2][4];
        ldsm4(a[0], aBase + kc * 32);
        ldsm4(a[1], aBase + 16 * AROW + kc * 32);
#pragma unroll
        for (int g = 0; g < 3; g++) {
            uint32_t b[4];
            ldsm4(b, bBase + g * 32 * AROW + kc * 32);
            uint32_t bj0[2] = {b[0], b[2]}, bj1[2] = {b[1], b[3]};
#pragma unroll
            for (int mt = 0; mt < 2; mt++) {
                mma16816(acc[mt][g][0], a[mt], bj0);
                mma16816(acc[mt][g][1], a[mt], bj1);
            }
        }
    }
}

// ---------------- prep ----------------
__global__ void prep_kernel(const float* __restrict__ W_ih, const float* __restrict__ W_hh,
                            const float* __restrict__ b_ih, const float* __restrict__ b_hh) {
    int idx = blockIdx.x * 256 + threadIdx.x;
    if (idx < 2 * UGN * 96 * 256) {
        int k = idx & 255, rest = idx >> 8;
        int j = rest % 96, ug = (rest / 96) & 7, m = rest / 768;
        int gate = j >> 5, u = j & 31;
        int orig = gate * 256 + ug * 32 + u;
        float wv = m ? W_hh[orig * 256 + k] : W_ih[orig * 256 + k];
        __half hi = __float2half_rn(wv);
        __half lo = __float2half_rn(wv - __half2float(hi));
        g_W[m][ug][0][j * 256 + k] = hi;
        g_W[m][ug][1][j * 256 + k] = lo;
    }
    if (idx < 256) {
        g_bias[idx]       = b_ih[idx]       + b_hh[idx];
        g_bias[256 + idx] = b_ih[256 + idx] + b_hh[256 + idx];
        g_bias[512 + idx] = b_ih[512 + idx];
        g_bias[768 + idx] = b_hh[512 + idx];
    }
    if (idx < Tsz * MGN) ((int*)g_flag)[idx] = 0;
}

// ---------------- phase A: xi = x @ W_hi^T, x fp16, output T-MAJOR ----------------
__global__ void __launch_bounds__(256, 1) xproj_kernel(const float* __restrict__ x) {
    extern __shared__ __align__(16) char sp[];
    const uint32_t sA = smem_u32(sp);
    const int tid = threadIdx.x, lane = tid & 31, w = tid >> 5;
    const int wm = w & 3, wn = w >> 2;
    const size_t bt0 = (size_t)blockIdx.x * 128;

    // x tile -> fp16 A (rows = 128 consecutive (b,t))
    const float4* x4 = (const float4*)(x + bt0 * 256);
    for (int i = tid; i < 8192; i += 256) {
        int row = i >> 6, c4 = i & 63;
        float4 v = __ldg(&x4[(size_t)row * 64 + c4]);
        uint2 hv = {h2u(__floats2half2_rn(v.x, v.y)), h2u(__floats2half2_rn(v.z, v.w))};
        *(uint2*)(sp + row * AROW + c4 * 8) = hv;
    }

#pragma unroll 1
    for (int ug = 0; ug < UGN; ug++) {
        float acc[2][3][2][4];
#pragma unroll
        for (int mt = 0; mt < 2; mt++)
#pragma unroll
            for (int g = 0; g < 3; g++)
#pragma unroll
                for (int j = 0; j < 2; j++)
#pragma unroll
                    for (int e = 0; e < 4; e++) acc[mt][g][j][e] = 0.0f;

        __syncthreads();  // A staged / previous gemm reads of W done
        for (int i = tid; i < 3072; i += 256) {
            int j = i >> 5, q = i & 31;
            *(uint4*)(sp + OFF_WX + j * AROW + q * 16) =
                ((const uint4*)&g_W[0][ug][0][0])[j * 32 + q];
        }
        __syncthreads();
        gemm2(sA, sA + OFF_WX, wm, wn, lane, acc);   // W_hi @ x

#pragma unroll
        for (int mt = 0; mt < 2; mt++)
#pragma unroll
            for (int eh = 0; eh < 2; eh++) {
                int rl = 32 * wm + 16 * mt + (lane >> 2) + 8 * eh;
                size_t bt = bt0 + rl;
                size_t bb = bt >> 9, tt = bt & 511;       // x is [b][t][I], T=512
                float* go = g_xi + (tt * Bsz + bb) * 768 + ug * 96 + wn * 16 + 2 * (lane & 3);
#pragma unroll
                for (int g = 0; g < 3; g++)
#pragma unroll
                    for (int j = 0; j < 2; j++) {
                        float2 v = {acc[mt][g][j][eh * 2], acc[mt][g][j][eh * 2 + 1]};
                        *(float2*)(go + g * 32 + j * 8) = v;
                    }
            }
    }
}

// ---------------- recurrence: 128 persistent CTAs, 512 threads (M=64, warp N=24) --------
__global__ void __launch_bounds__(512, 1) gru_rec(const int* __restrict__ seqlen,
                                                  float* __restrict__ out) {
    extern __shared__ __align__(16) char sp[];
    const uint32_t sA = smem_u32(sp);
    const int tid = threadIdx.x, lane = tid & 31, w = tid >> 5;
    const int wm = w & 3, wn = w >> 2;                 // wm: 16-row block, wn: 8-unit block
    const int l16 = lane & 15, h16 = (lane >> 4) & 1;
    const int bg = blockIdx.x >> 3, ug = blockIdx.x & 7;

    // W_hh hi resident all steps
    for (int i = tid; i < 3072; i += 512) {
        int j = i >> 5, q = i & 31;
        *(uint4*)(sp + OFF_W + j * AROW + q * 16) =
            ((const uint4*)&g_W[1][ug][0][0])[j * 32 + q];
    }
    // A = 0 (h0)
    {
        uint4 z = {0, 0, 0, 0};
        for (int i = tid; i < 2112; i += 512) ((uint4*)sp)[i] = z;
    }

    // thread-resident biases (2 units) and seqlen (2 rows)
    const int ucol = 8 * wn + 2 * (lane & 3);          // first of thread's 2 unit-cols
    float br[2], bz[2], bxn[2], bhg[2];
#pragma unroll
    for (int e1 = 0; e1 < 2; e1++) {
        int hu = ug * 32 + ucol + e1;
        br[e1] = g_bias[hu]; bz[e1] = g_bias[256 + hu];
        bxn[e1] = g_bias[512 + hu]; bhg[e1] = g_bias[768 + hu];
    }
    const int row0 = 16 * wm + (lane >> 2);
    int Lr[2];
    Lr[0] = seqlen[bg * 64 + row0];
    Lr[1] = seqlen[bg * 64 + row0 + 8];

    float hold[2][2], hn[2][2];
#pragma unroll
    for (int eh = 0; eh < 2; eh++)
#pragma unroll
        for (int e1 = 0; e1 < 2; e1++) { hold[eh][e1] = 0.0f; hn[eh][e1] = 0.0f; }
    __syncthreads();

    const uint32_t aBase = sA + (16 * wm + l16) * AROW + h16 * 16;
    const uint32_t bRow  = (8 * wn + (lane & 7)) * AROW + ((l16 >> 3) & 1) * 16;

#pragma unroll 1
    for (int t = 0; t < Tsz; t++) {
        // xi preload FIRST (t-major: contiguous CTA block, full sectors);
        // memory latency hides behind the flag wait
        float2 xif[2][3];
#pragma unroll
        for (int eh = 0; eh < 2; eh++) {
            const float* xb = g_xi + ((size_t)t * Bsz + bg * 64 + row0 + 8 * eh) * 768 +
                              ug * 96 + ucol;
#pragma unroll
            for (int g = 0; g < 3; g++)
                xif[eh][g] = __ldg((const float2*)(xb + g * 32));
        }

        if (t > 0) {
            // elected-warp spin: one L2 poll stream per CTA
            if (w == 0) {
                const int* fp = &g_flag[t - 1][bg];
                int v;
                do { asm volatile("ld.global.acquire.gpu.b32 %0, [%1];" : "=r"(v) : "l"(fp)); }
                while (v < UGN);
            }
            __syncthreads();  // propagate acquire CTA-wide

            // stage h (fp16) -> A via cp.async (g_hx row = 32 uint4)
            const uint4* hr = (const uint4*)(g_hx[(t - 1) & 1] + (size_t)(bg * 64) * 256);
            for (int i = tid; i < 2048; i += 512) {
                int row = i >> 5, q = i & 31;
                cpasync16(sA + row * AROW + q * 16, hr + (size_t)row * 32 + q);
            }
            asm volatile("cp.async.commit_group;");
            asm volatile("cp.async.wait_group 0;" ::: "memory");
        }
        __syncthreads();

        float acc[3][4];
#pragma unroll
        for (int g = 0; g < 3; g++)
#pragma unroll
            for (int e = 0; e < 4; e++) acc[g][e] = 0.0f;

        // single-pass GEMM: per kc, per gate: W_hi @ h
#pragma unroll 4
        for (int kc = 0; kc < 16; kc++) {
            uint32_t ah[4];
            ldsm4(ah, aBase + kc * 32);
#pragma unroll
            for (int g = 0; g < 3; g++) {
                uint32_t bh[2];
                ldsm2(bh, sA + OFF_W + g * 32 * AROW + bRow + kc * 32);
                mma16816(acc[g], ah, bh);
            }
        }

        // epilogue: gates + h update (hold stays fp32); publish fp16 h to g_hx
#pragma unroll
        for (int eh = 0; eh < 2; eh++) {
            float hv2[2];
#pragma unroll
            for (int e1 = 0; e1 < 2; e1++) {
                int e = 2 * eh + e1;
                float xr = e1 ? xif[eh][0].y : xif[eh][0].x;
                float xz = e1 ? xif[eh][1].y : xif[eh][1].x;
                float xn = e1 ? xif[eh][2].y : xif[eh][2].x;
                float rr = sigm(acc[0][e] + xr + br[e1]);
                float zz = sigm(acc[1][e] + xz + bz[e1]);
                float nn = tanh_(xn + bxn[e1] + rr * (acc[2][e] + bhg[e1]));
                float hv = zz * (hold[eh][e1] - nn) + nn;
                hold[eh][e1] = hv;
                if (t + 1 == Lr[eh]) hn[eh][e1] = hv;
                hv2[e1] = hv;
            }
            __half* hd = g_hx[t & 1] + (size_t)(bg * 64 + row0 + 8 * eh) * 256 + ug * 32 + ucol;
            *(uint32_t*)hd = h2u(__floats2half2_rn(hv2[0], hv2[1]));
        }
        __syncthreads();   // publishes done + all A-tile reads done (safe to restage)
        if (tid == 0) {
            __threadfence();            // release: bar made CTA stores visible to tid0's fence
            atomicAdd(&g_flag[t][bg], 1);
        }
    }

#pragma unroll
    for (int eh = 0; eh < 2; eh++)
#pragma unroll
        for (int e1 = 0; e1 < 2; e1++)
            out[(size_t)(bg * 64 + row0 + 8 * eh) * 256 + ug * 32 + ucol + e1] = hn[eh][e1];
}

extern "C" void kernel_launch(void* const* d_in, const int* in_sizes, int n_in,
                              void* d_out, int out_size) {
    const float* x      = (const float*)d_in[0];
    const int*   seqlen = (const int*)d_in[1];
    const float* W_ih   = (const float*)d_in[2];
    const float* W_hh   = (const float*)d_in[3];
    const float* b_ih   = (const float*)d_in[4];
    const float* b_hh   = (const float*)d_in[5];
    float*       out    = (float*)d_out;

    static bool init = false;
    if (!init) {
        cudaFuncSetAttribute(xproj_kernel, cudaFuncAttributeMaxDynamicSharedMemorySize, SMEM_XP);
        cudaFuncSetAttribute(gru_rec, cudaFuncAttributeMaxDynamicSharedMemorySize, SMEM_REC);
        init = true;
    }
    prep_kernel<<<1536, 256>>>(W_ih, W_hh, b_ih, b_hh);
    xproj_kernel<<<(Bsz * Tsz) / 128, 256, SMEM_XP>>>(x);
    gru_rec<<<MGN * UGN, 512, SMEM_REC>>>(seqlen, out);
}